// round 8
// baseline (speedup 1.0000x reference)
#include <cuda_runtime.h>
#include <cstdint>

#define BB 4
#define SS 1024
#define EE 1024
#define HH 16
#define DD 64
#define NE3 3072
static constexpr float ATT_SCALE = 0.125f; // 1/sqrt(64)

// Scratch (no allocations allowed)
__device__ float g_Q[BB*HH*SS*DD];
__device__ float g_K[BB*HH*SS*DD];
__device__ float g_V[BB*HH*SS*DD];
__device__ float g_O[BB*HH*SS*DD];
__device__ float g_X[BB*SS*EE];     // tf32-rounded X
__device__ float g_WqT[NE3*EE];     // Wqkv transposed [n][k], tf32-rounded
__device__ float g_WoT[EE*EE];      // Wo transposed [n][k], tf32-rounded

// f32 -> tf32 round-to-nearest
__device__ __forceinline__ uint32_t f2tf(float x) {
    uint32_t r;
    asm("cvt.rna.tf32.f32 %0, %1;" : "=r"(r) : "f"(x));
    return r;
}

__device__ __forceinline__ void mma_tf32(float* c, const uint32_t* a, const uint32_t* b) {
    asm volatile(
        "mma.sync.aligned.m16n8k8.row.col.f32.tf32.tf32.f32 "
        "{%0,%1,%2,%3},{%4,%5,%6,%7},{%8,%9},{%0,%1,%2,%3};"
        : "+f"(c[0]), "+f"(c[1]), "+f"(c[2]), "+f"(c[3])
        : "r"(a[0]), "r"(a[1]), "r"(a[2]), "r"(a[3]), "r"(b[0]), "r"(b[1]));
}

__device__ __forceinline__ void ldsm_x4(uint32_t* r, uint32_t addr) {
    asm volatile("ldmatrix.sync.aligned.m8n8.x4.shared.b16 {%0,%1,%2,%3}, [%4];"
                 : "=r"(r[0]), "=r"(r[1]), "=r"(r[2]), "=r"(r[3]) : "r"(addr));
}
__device__ __forceinline__ void ldsm_x2(uint32_t* r, uint32_t addr) {
    asm volatile("ldmatrix.sync.aligned.m8n8.x2.shared.b16 {%0,%1}, [%2];"
                 : "=r"(r[0]), "=r"(r[1]) : "r"(addr));
}

__device__ __forceinline__ void cp_async16(uint32_t saddr, const void* gaddr) {
    asm volatile("cp.async.cg.shared.global [%0], [%1], 16;"
                 :: "r"(saddr), "l"(gaddr));
}
#define CP_COMMIT() asm volatile("cp.async.commit_group;")
#define CP_WAIT1()  asm volatile("cp.async.wait_group 1;")
#define CP_WAIT0()  asm volatile("cp.async.wait_group 0;")

// ---------------------------------------------------------------------------
// Pre-pass kernels: tf32-round (and transpose for weights).
// ---------------------------------------------------------------------------
__global__ __launch_bounds__(256) void round_x_kernel(
    const float* __restrict__ in, float* __restrict__ out, int n4)
{
    int i = blockIdx.x * blockDim.x + threadIdx.x;
    if (i < n4) {
        float4 v = ((const float4*)in)[i];
        uint4 r = {f2tf(v.x), f2tf(v.y), f2tf(v.z), f2tf(v.w)};
        ((uint4*)out)[i] = r;
    }
}

// out[n][k] = round(in[k][n]); in is [K][N] row-major
__global__ __launch_bounds__(256) void transpose_round_kernel(
    const float* __restrict__ in, float* __restrict__ out, int K, int N)
{
    __shared__ float t[32][33];
    const int n0 = blockIdx.x * 32, k0 = blockIdx.y * 32;
    for (int i = threadIdx.y; i < 32; i += 8)
        t[i][threadIdx.x] = in[(size_t)(k0 + i) * N + n0 + threadIdx.x];
    __syncthreads();
    for (int i = threadIdx.y; i < 32; i += 8)
        out[(size_t)(n0 + i) * K + k0 + threadIdx.x] =
            __uint_as_float(f2tf(t[threadIdx.x][i]));
}

// ---------------------------------------------------------------------------
// GEMM geometry: block 128x128, BK=16, 8 warps (4m x 2n), warp tile 32x64.
// Smem (pre-rounded f32): A [m][k] stride 20, B [n][k] stride 20.
// Fragments via ldmatrix (b16-aliased): conflict-free (rows stride 20).
// cp.async double-buffered, R5-proven pipeline.
// ---------------------------------------------------------------------------

// Kernel 1: QKV GEMM -> scatter to g_Q/K/V (rounded to tf32 at store)
__global__ __launch_bounds__(256, 2) void qkv_gemm_tc(
    const float* __restrict__ bias)
{
    __shared__ float As[2][128 * 20];
    __shared__ float Bs[2][128 * 20];

    const int tid  = threadIdx.x;
    const int lane = tid & 31;
    const int warp = tid >> 5;
    const int wm   = warp >> 1;
    const int wn   = warp & 1;
    const int gid  = lane >> 2;
    const int tig  = lane & 3;
    const int rBase = blockIdx.y * 128;
    const int cBase = blockIdx.x * 128;

    float acc[2][8][4];
#pragma unroll
    for (int i = 0; i < 2; i++)
#pragma unroll
        for (int j = 0; j < 8; j++)
#pragma unroll
            for (int k = 0; k < 4; k++) acc[i][j][k] = 0.f;

    // cp.async mapping
    const int am = tid >> 2;
    const int ak = (tid & 3) * 4;
    const int bn = tid & 127;
    const int bk = (tid >> 7) * 8;

    const float* Ag0 = g_X + (size_t)(rBase + am) * EE + ak;
    const float* Ag1 = g_X + (size_t)(rBase + am + 64) * EE + ak;
    const float* BgT = g_WqT + (size_t)(cBase + bn) * EE + bk;

    const uint32_t sA = (uint32_t)__cvta_generic_to_shared(&As[0][0]);
    const uint32_t sB = (uint32_t)__cvta_generic_to_shared(&Bs[0][0]);
    const uint32_t sA0 = sA + (am * 20 + ak) * 4;
    const uint32_t sA1 = sA + ((am + 64) * 20 + ak) * 4;
    const uint32_t sB0 = sB + (bn * 20 + bk) * 4;
    const uint32_t stA = 128 * 20 * 4;
    const uint32_t stB = 128 * 20 * 4;

    auto loadTile = [&](int buf, int k0) {
        cp_async16(sA0 + buf * stA, Ag0 + k0);
        cp_async16(sA1 + buf * stA, Ag1 + k0);
        cp_async16(sB0 + buf * stB, BgT + k0);
        cp_async16(sB0 + 16 + buf * stB, BgT + k0 + 4);
    };

    // ldmatrix per-lane addresses
    const int aRowOff = (lane & 7) + ((lane >> 3) & 1) * 8;
    const int aColOff = (lane >> 4) * 4;
    const uint32_t aAddr = sA + ((wm * 32 + aRowOff) * 20 + aColOff) * 4;
    const int bRowOff = lane & 7;                  // lanes 0-15 used
    const int bColOff = ((lane >> 3) & 1) * 4;
    const uint32_t bAddr = sB + ((wn * 64 + bRowOff) * 20 + bColOff) * 4;

    loadTile(0, 0);
    CP_COMMIT();

    for (int it = 0; it < 64; ++it) {
        if (it + 1 < 64) {
            loadTile((it + 1) & 1, (it + 1) * 16);
            CP_COMMIT();
            CP_WAIT1();
        } else {
            CP_WAIT0();
        }
        __syncthreads();
        const uint32_t offA = (it & 1) * stA;
        const uint32_t offB = (it & 1) * stB;
#pragma unroll
        for (int ks = 0; ks < 2; ks++) {
            uint32_t af[2][4];
            ldsm_x4(af[0], aAddr + offA + ks * 32);
            ldsm_x4(af[1], aAddr + offA + 16 * 20 * 4 + ks * 32);
            uint32_t bf[8][2];
#pragma unroll
            for (int nt = 0; nt < 8; nt++)
                ldsm_x2(bf[nt], bAddr + offB + nt * 8 * 20 * 4 + ks * 32);
#pragma unroll
            for (int mt = 0; mt < 2; mt++)
#pragma unroll
                for (int nt = 0; nt < 8; nt++)
                    mma_tf32(acc[mt][nt], af[mt], bf[nt]);
        }
        __syncthreads();
    }

    // epilogue: bias + tf32-round + scatter into Q/K/V [B,H,S,D]
#pragma unroll
    for (int mt = 0; mt < 2; mt++)
#pragma unroll
        for (int nt = 0; nt < 8; nt++)
#pragma unroll
            for (int half = 0; half < 2; half++) {
                const int r = rBase + wm * 32 + mt * 16 + gid + half * 8;
                const int c = cBase + wn * 64 + nt * 8 + 2 * tig;
                float2 v;
                v.x = __uint_as_float(f2tf(acc[mt][nt][half * 2 + 0] + bias[c]));
                v.y = __uint_as_float(f2tf(acc[mt][nt][half * 2 + 1] + bias[c + 1]));
                const int b_ = r >> 10, s_ = r & 1023;
                const int which = c >> 10;
                const int e = c & 1023;
                const int h = e >> 6, d = e & 63;
                float* dst = (which == 0) ? g_Q : (which == 1) ? g_K : g_V;
                *(float2*)&dst[(((size_t)(b_ * HH + h)) * SS + s_) * DD + d] = v;
            }
}

// ---------------------------------------------------------------------------
// Kernel 2: causal flash attention, tf32 mma, QT=64 (4 warps), KT=32.
// All inputs pre-rounded -> raw fragment loads, zero cvts in the loop.
// K/V double-buffered via cp.async (R7-proven).
// ---------------------------------------------------------------------------
#define QT 64
#define KT 32
__global__ __launch_bounds__(128) void flash_attn_tc()
{
    __shared__ float Ks[2][KT][68];
    __shared__ float Vs[2][KT][72];
    __shared__ float Ps[4][16][KT + 4];

    const int tid  = threadIdx.x;
    const int lane = tid & 31;
    const int warp = tid >> 5;
    const int gid  = lane >> 2;
    const int tig  = lane & 3;
    const int bh   = blockIdx.y;
    const int q0   = blockIdx.x * QT;
    const int r0   = q0 + warp * 16 + gid;
    const int r1   = r0 + 8;

    uint32_t qa[8][4];
    {
        const float* Qb = g_Q + ((size_t)bh * SS) * DD;   // pre-rounded
#pragma unroll
        for (int ks = 0; ks < 8; ks++) {
            qa[ks][0] = __float_as_uint(Qb[(size_t)r0 * DD + ks * 8 + tig] * ATT_SCALE);
            qa[ks][1] = __float_as_uint(Qb[(size_t)r1 * DD + ks * 8 + tig] * ATT_SCALE);
            qa[ks][2] = __float_as_uint(Qb[(size_t)r0 * DD + ks * 8 + tig + 4] * ATT_SCALE);
            qa[ks][3] = __float_as_uint(Qb[(size_t)r1 * DD + ks * 8 + tig + 4] * ATT_SCALE);
        }
    }

    float m0 = -1e30f, m1 = -1e30f, l0 = 0.f, l1 = 0.f;
    float oa[8][4];
#pragma unroll
    for (int i = 0; i < 8; i++)
#pragma unroll
        for (int j = 0; j < 4; j++) oa[i][j] = 0.f;

    const float* Kb = g_K + ((size_t)bh * SS) * DD;
    const float* Vb = g_V + ((size_t)bh * SS) * DD;
    const uint32_t sK = (uint32_t)__cvta_generic_to_shared(&Ks[0][0][0]);
    const uint32_t sV = (uint32_t)__cvta_generic_to_shared(&Vs[0][0][0]);
    const uint32_t stK = KT * 68 * 4;
    const uint32_t stV = KT * 72 * 4;

    auto loadTile = [&](int buf, int k0) {
#pragma unroll
        for (int i = 0; i < 4; i++) {
            const int idx = tid + i * 128;
            const int key = idx >> 4;
            const int c4  = (idx & 15) * 4;
            cp_async16(sK + buf * stK + (key * 68 + c4) * 4,
                       Kb + (size_t)(k0 + key) * DD + c4);
            cp_async16(sV + buf * stV + (key * 72 + c4) * 4,
                       Vb + (size_t)(k0 + key) * DD + c4);
        }
    };

    const int nkt = (blockIdx.x + 1) * (QT / KT);
    loadTile(0, 0);
    CP_COMMIT();

    for (int kt = 0; kt < nkt; kt++) {
        if (kt + 1 < nkt) {
            loadTile((kt + 1) & 1, (kt + 1) * KT);
            CP_COMMIT();
            CP_WAIT1();
        } else {
            CP_WAIT0();
        }
        __syncthreads();
        const float (*Kt)[68] = Ks[kt & 1];
        const float (*Vt)[72] = Vs[kt & 1];
        const int k0 = kt * KT;

        float sc[4][4];
#pragma unroll
        for (int i = 0; i < 4; i++)
#pragma unroll
            for (int j = 0; j < 4; j++) sc[i][j] = 0.f;
#pragma unroll
        for (int ks = 0; ks < 8; ks++) {
#pragma unroll
            for (int snt = 0; snt < 4; snt++) {
                uint32_t bf[2];
                bf[0] = __float_as_uint(Kt[snt * 8 + gid][ks * 8 + tig]);
                bf[1] = __float_as_uint(Kt[snt * 8 + gid][ks * 8 + tig + 4]);
                mma_tf32(sc[snt], qa[ks], bf);
            }
        }

        float mt0 = -1e30f, mt1 = -1e30f;
#pragma unroll
        for (int snt = 0; snt < 4; snt++) {
            const int c0 = k0 + snt * 8 + 2 * tig;
            if (c0 > r0)     sc[snt][0] = -1e30f;
            if (c0 + 1 > r0) sc[snt][1] = -1e30f;
            if (c0 > r1)     sc[snt][2] = -1e30f;
            if (c0 + 1 > r1) sc[snt][3] = -1e30f;
            mt0 = fmaxf(mt0, fmaxf(sc[snt][0], sc[snt][1]));
            mt1 = fmaxf(mt1, fmaxf(sc[snt][2], sc[snt][3]));
        }
        mt0 = fmaxf(mt0, __shfl_xor_sync(0xffffffffu, mt0, 1));
        mt0 = fmaxf(mt0, __shfl_xor_sync(0xffffffffu, mt0, 2));
        mt1 = fmaxf(mt1, __shfl_xor_sync(0xffffffffu, mt1, 1));
        mt1 = fmaxf(mt1, __shfl_xor_sync(0xffffffffu, mt1, 2));

        const float nm0 = fmaxf(m0, mt0);
        const float nm1 = fmaxf(m1, mt1);
        const float al0 = __expf(m0 - nm0);
        const float al1 = __expf(m1 - nm1);
        m0 = nm0; m1 = nm1;

        float s0 = 0.f, s1 = 0.f;
#pragma unroll
        for (int snt = 0; snt < 4; snt++) {
            float p0 = __expf(sc[snt][0] - nm0);
            float p1 = __expf(sc[snt][1] - nm0);
            float p2 = __expf(sc[snt][2] - nm1);
            float p3 = __expf(sc[snt][3] - nm1);
            s0 += p0 + p1; s1 += p2 + p3;
            const int col = snt * 8 + 2 * tig;
            float2 w0 = {__uint_as_float(f2tf(p0)), __uint_as_float(f2tf(p1))};
            float2 w1 = {__uint_as_float(f2tf(p2)), __uint_as_float(f2tf(p3))};
            *(float2*)&Ps[warp][gid][col] = w0;
            *(float2*)&Ps[warp][gid + 8][col] = w1;
        }
        s0 += __shfl_xor_sync(0xffffffffu, s0, 1);
        s0 += __shfl_xor_sync(0xffffffffu, s0, 2);
        s1 += __shfl_xor_sync(0xffffffffu, s1, 1);
        s1 += __shfl_xor_sync(0xffffffffu, s1, 2);
        l0 = l0 * al0 + s0;
        l1 = l1 * al1 + s1;

#pragma unroll
        for (int dnt = 0; dnt < 8; dnt++) {
            oa[dnt][0] *= al0; oa[dnt][1] *= al0;
            oa[dnt][2] *= al1; oa[dnt][3] *= al1;
        }
        __syncwarp();

#pragma unroll
        for (int ks = 0; ks < 4; ks++) {
            uint32_t af[4];
            af[0] = __float_as_uint(Ps[warp][gid][ks * 8 + tig]);
            af[1] = __float_as_uint(Ps[warp][gid + 8][ks * 8 + tig]);
            af[2] = __float_as_uint(Ps[warp][gid][ks * 8 + tig + 4]);
            af[3] = __float_as_uint(Ps[warp][gid + 8][ks * 8 + tig + 4]);
#pragma unroll
            for (int dnt = 0; dnt < 8; dnt++) {
                uint32_t bf[2];
                bf[0] = __float_as_uint(Vt[ks * 8 + tig][dnt * 8 + gid]);
                bf[1] = __float_as_uint(Vt[ks * 8 + tig + 4][dnt * 8 + gid]);
                mma_tf32(oa[dnt], af, bf);
            }
        }
        __syncthreads();
    }

    const float inv0 = 1.f / l0;
    const float inv1 = 1.f / l1;
    float* Ob = g_O + ((size_t)bh * SS) * DD;
#pragma unroll
    for (int dnt = 0; dnt < 8; dnt++) {
        const int col = dnt * 8 + 2 * tig;
        float2 v0 = {__uint_as_float(f2tf(oa[dnt][0] * inv0)),
                     __uint_as_float(f2tf(oa[dnt][1] * inv0))};
        float2 v1 = {__uint_as_float(f2tf(oa[dnt][2] * inv1)),
                     __uint_as_float(f2tf(oa[dnt][3] * inv1))};
        *(float2*)&Ob[(size_t)r0 * DD + col] = v0;
        *(float2*)&Ob[(size_t)r1 * DD + col] = v1;
    }
}

// ---------------------------------------------------------------------------
// Kernel 3: output projection (tf32 mma, ldmatrix, pre-rounded inputs).
// A gathered from g_O [B,H,S,D], B from g_WoT [n][k].
// ---------------------------------------------------------------------------
__global__ __launch_bounds__(256, 2) void out_gemm_tc(
    const float* __restrict__ bias, float* __restrict__ out)
{
    __shared__ float As[2][128 * 20];
    __shared__ float Bs[2][128 * 20];

    const int tid  = threadIdx.x;
    const int lane = tid & 31;
    const int warp = tid >> 5;
    const int wm   = warp >> 1;
    const int wn   = warp & 1;
    const int gid  = lane >> 2;
    const int tig  = lane & 3;
    const int rBase = blockIdx.y * 128;
    const int cBase = blockIdx.x * 128;

    float acc[2][8][4];
#pragma unroll
    for (int i = 0; i < 2; i++)
#pragma unroll
        for (int j = 0; j < 8; j++)
#pragma unroll
            for (int k = 0; k < 4; k++) acc[i][j][k] = 0.f;

    const int am = tid >> 2;
    const int ak = (tid & 3) * 4;
    const int bn = tid & 127;
    const int bk = (tid >> 7) * 8;

    const int r0 = rBase + am;
    const int r1 = rBase + am + 64;
    const int b0_ = r0 >> 10, s0_ = r0 & 1023;
    const int b1_ = r1 >> 10, s1_ = r1 & 1023;
    const float* BgT = g_WoT + (size_t)(cBase + bn) * EE + bk;

    const uint32_t sA = (uint32_t)__cvta_generic_to_shared(&As[0][0]);
    const uint32_t sB = (uint32_t)__cvta_generic_to_shared(&Bs[0][0]);
    const uint32_t sA0 = sA + (am * 20 + ak) * 4;
    const uint32_t sA1 = sA + ((am + 64) * 20 + ak) * 4;
    const uint32_t sB0 = sB + (bn * 20 + bk) * 4;
    const uint32_t stA = 128 * 20 * 4;
    const uint32_t stB = 128 * 20 * 4;

    auto loadTile = [&](int buf, int k0) {
        const int k = k0 + ak;
        const int h = k >> 6, d = k & 63;
        cp_async16(sA0 + buf * stA,
                   g_O + (((size_t)(b0_ * HH + h)) * SS + s0_) * DD + d);
        cp_async16(sA1 + buf * stA,
                   g_O + (((size_t)(b1_ * HH + h)) * SS + s1_) * DD + d);
        cp_async16(sB0 + buf * stB, BgT + k0);
        cp_async16(sB0 + 16 + buf * stB, BgT + k0 + 4);
    };

    const int aRowOff = (lane & 7) + ((lane >> 3) & 1) * 8;
    const int aColOff = (lane >> 4) * 4;
    const uint32_t aAddr = sA + ((wm * 32 + aRowOff) * 20 + aColOff) * 4;
    const int bRowOff = lane & 7;
    const int bColOff = ((lane >> 3) & 1) * 4;
    const uint32_t bAddr = sB + ((wn * 64 + bRowOff) * 20 + bColOff) * 4;

    loadTile(0, 0);
    CP_COMMIT();

    for (int it = 0; it < 64; ++it) {
        if (it + 1 < 64) {
            loadTile((it + 1) & 1, (it + 1) * 16);
            CP_COMMIT();
            CP_WAIT1();
        } else {
            CP_WAIT0();
        }
        __syncthreads();
        const uint32_t offA = (it & 1) * stA;
        const uint32_t offB = (it & 1) * stB;
#pragma unroll
        for (int ks = 0; ks < 2; ks++) {
            uint32_t af[2][4];
            ldsm_x4(af[0], aAddr + offA + ks * 32);
            ldsm_x4(af[1], aAddr + offA + 16 * 20 * 4 + ks * 32);
            uint32_t bf[8][2];
#pragma unroll
            for (int nt = 0; nt < 8; nt++)
                ldsm_x2(bf[nt], bAddr + offB + nt * 8 * 20 * 4 + ks * 32);
#pragma unroll
            for (int mt = 0; mt < 2; mt++)
#pragma unroll
                for (int nt = 0; nt < 8; nt++)
                    mma_tf32(acc[mt][nt], af[mt], bf[nt]);
        }
        __syncthreads();
    }

#pragma unroll
    for (int mt = 0; mt < 2; mt++)
#pragma unroll
        for (int nt = 0; nt < 8; nt++)
#pragma unroll
            for (int half = 0; half < 2; half++) {
                const int r = rBase + wm * 32 + mt * 16 + gid + half * 8;
                const int c = cBase + wn * 64 + nt * 8 + 2 * tig;
                float2 v;
                v.x = acc[mt][nt][half * 2 + 0] + bias[c];
                v.y = acc[mt][nt][half * 2 + 1] + bias[c + 1];
                *(float2*)&out[(size_t)r * EE + c] = v;
            }
}

// ---------------------------------------------------------------------------
extern "C" void kernel_launch(void* const* d_in, const int* in_sizes, int n_in,
                              void* d_out, int out_size)
{
    const float* x = (const float*)d_in[0];
    const float* Wqkv = (const float*)d_in[2];
    const float* bqkv = (const float*)d_in[3];
    const float* Wo = (const float*)d_in[4];
    const float* bo = (const float*)d_in[5];
    float* out = (float*)d_out;

    float* gX;  cudaGetSymbolAddress((void**)&gX,  g_X);
    float* gWq; cudaGetSymbolAddress((void**)&gWq, g_WqT);
    float* gWo; cudaGetSymbolAddress((void**)&gWo, g_WoT);

    // pre-pass: tf32-round X, transpose+round weights
    round_x_kernel<<<(BB*SS*EE/4 + 255)/256, 256>>>(x, gX, BB*SS*EE/4);
    {
        dim3 grid(NE3/32, EE/32);
        transpose_round_kernel<<<grid, dim3(32,8)>>>(Wqkv, gWq, EE, NE3);
    }
    {
        dim3 grid(EE/32, EE/32);
        transpose_round_kernel<<<grid, dim3(32,8)>>>(Wo, gWo, EE, EE);
    }
    {
        dim3 grid(NE3 / 128, (BB * SS) / 128);   // (24, 32)
        qkv_gemm_tc<<<grid, 256>>>(bqkv);
    }
    {
        dim3 grid(SS / QT, BB * HH);             // (16, 64)
        flash_attn_tc<<<grid, 128>>>();
    }
    {
        dim3 grid(EE / 128, (BB * SS) / 128);    // (8, 32)
        out_gemm_tc<<<grid, 256>>>(bo, out);
    }
}

// round 9
// speedup vs baseline: 1.2498x; 1.2498x over previous
#include <cuda_runtime.h>
#include <cstdint>

#define BB 4
#define SS 1024
#define EE 1024
#define HH 16
#define DD 64
#define NE3 3072
static constexpr float ATT_SCALE = 0.125f; // 1/sqrt(64), exact in tf32

// Scratch (no allocations allowed)
__device__ float g_Q[BB*HH*SS*DD];
__device__ float g_K[BB*HH*SS*DD];
__device__ float g_V[BB*HH*SS*DD];
__device__ float g_O[BB*HH*SS*DD];
__device__ float g_X[BB*SS*EE];     // tf32-rounded X
__device__ float g_Wq[EE*NE3];      // tf32-rounded Wqkv (same [k][n] layout)
__device__ float g_Wo[EE*EE];       // tf32-rounded Wo

// f32 -> tf32 round-to-nearest
__device__ __forceinline__ uint32_t f2tf(float x) {
    uint32_t r;
    asm("cvt.rna.tf32.f32 %0, %1;" : "=r"(r) : "f"(x));
    return r;
}

__device__ __forceinline__ void mma_tf32(float* c, const uint32_t* a, const uint32_t* b) {
    asm volatile(
        "mma.sync.aligned.m16n8k8.row.col.f32.tf32.tf32.f32 "
        "{%0,%1,%2,%3},{%4,%5,%6,%7},{%8,%9},{%0,%1,%2,%3};"
        : "+f"(c[0]), "+f"(c[1]), "+f"(c[2]), "+f"(c[3])
        : "r"(a[0]), "r"(a[1]), "r"(a[2]), "r"(a[3]), "r"(b[0]), "r"(b[1]));
}

__device__ __forceinline__ void cp_async16(uint32_t saddr, const void* gaddr) {
    asm volatile("cp.async.cg.shared.global [%0], [%1], 16;"
                 :: "r"(saddr), "l"(gaddr));
}
#define CP_COMMIT() asm volatile("cp.async.commit_group;")
#define CP_WAIT1()  asm volatile("cp.async.wait_group 1;")
#define CP_WAIT0()  asm volatile("cp.async.wait_group 0;")

// ---------------------------------------------------------------------------
// Pre-pass: elementwise tf32-round (coalesced, no transpose).
// ---------------------------------------------------------------------------
__global__ __launch_bounds__(256) void round_kernel(
    const float* __restrict__ in, float* __restrict__ out, int n4)
{
    int i = blockIdx.x * blockDim.x + threadIdx.x;
    if (i < n4) {
        float4 v = ((const float4*)in)[i];
        uint4 r = {f2tf(v.x), f2tf(v.y), f2tf(v.z), f2tf(v.w)};
        ((uint4*)out)[i] = r;
    }
}

// ---------------------------------------------------------------------------
// GEMM geometry (R7-proven): block 128x128, BK=16, 8 warps (4m x 2n),
// warp tile 32x64 = 2x8 m16n8k8 tf32 mma.
// Smem (pre-rounded f32): A [m][k] stride 20, B [k][n] stride 136.
// Fragment loads are raw LDS (no cvt). cp.async double-buffered pipeline:
//   issue loads(it+1) -> commit -> WAIT1 -> sync -> compute(it) -> sync.
// ---------------------------------------------------------------------------

// Kernel 1: QKV GEMM -> scatter to g_Q/K/V (tf32-rounded at store)
__global__ __launch_bounds__(256, 2) void qkv_gemm_tc(
    const float* __restrict__ bias)
{
    __shared__ float As[2][128 * 20];
    __shared__ float Bs[2][16 * 136];

    const int tid  = threadIdx.x;
    const int lane = tid & 31;
    const int warp = tid >> 5;
    const int wm   = warp >> 1;
    const int wn   = warp & 1;
    const int gid  = lane >> 2;
    const int tig  = lane & 3;
    const int rBase = blockIdx.y * 128;
    const int cBase = blockIdx.x * 128;

    float acc[2][8][4];
#pragma unroll
    for (int i = 0; i < 2; i++)
#pragma unroll
        for (int j = 0; j < 8; j++)
#pragma unroll
            for (int k = 0; k < 4; k++) acc[i][j][k] = 0.f;

    const int am = tid >> 2;
    const int ak = (tid & 3) * 4;
    const int kb = tid >> 5;
    const int nb = (tid & 31) * 4;

    const float* Ag0 = g_X + (size_t)(rBase + am) * EE + ak;
    const float* Ag1 = g_X + (size_t)(rBase + am + 64) * EE + ak;
    const float* Bg0 = g_Wq + (size_t)kb * NE3 + cBase + nb;
    const float* Bg1 = g_Wq + (size_t)(kb + 8) * NE3 + cBase + nb;

    const uint32_t sA = (uint32_t)__cvta_generic_to_shared(&As[0][0]);
    const uint32_t sB = (uint32_t)__cvta_generic_to_shared(&Bs[0][0]);
    const uint32_t sA0 = sA + (am * 20 + ak) * 4;
    const uint32_t sA1 = sA + ((am + 64) * 20 + ak) * 4;
    const uint32_t sB0 = sB + (kb * 136 + nb) * 4;
    const uint32_t sB1 = sB + ((kb + 8) * 136 + nb) * 4;
    const uint32_t stA = 128 * 20 * 4;
    const uint32_t stB = 16 * 136 * 4;

    auto loadTile = [&](int buf, int k0) {
        cp_async16(sA0 + buf * stA, Ag0 + k0);
        cp_async16(sA1 + buf * stA, Ag1 + k0);
        cp_async16(sB0 + buf * stB, Bg0 + (size_t)k0 * NE3);
        cp_async16(sB1 + buf * stB, Bg1 + (size_t)k0 * NE3);
    };

    loadTile(0, 0);
    CP_COMMIT();

    for (int it = 0; it < 64; ++it) {
        if (it + 1 < 64) {
            loadTile((it + 1) & 1, (it + 1) * 16);
            CP_COMMIT();
            CP_WAIT1();
        } else {
            CP_WAIT0();
        }
        __syncthreads();
        {
            const float* Ab = As[it & 1];
            const float* Bb = Bs[it & 1];
#pragma unroll
            for (int ks = 0; ks < 2; ks++) {
                uint32_t af[2][4];
#pragma unroll
                for (int mt = 0; mt < 2; mt++) {
                    const int base = (wm * 32 + mt * 16 + gid) * 20 + ks * 8 + tig;
                    af[mt][0] = __float_as_uint(Ab[base]);
                    af[mt][1] = __float_as_uint(Ab[base + 160]);
                    af[mt][2] = __float_as_uint(Ab[base + 4]);
                    af[mt][3] = __float_as_uint(Ab[base + 164]);
                }
                uint32_t bf[8][2];
#pragma unroll
                for (int nt = 0; nt < 8; nt++) {
                    const int col = wn * 64 + nt * 8 + gid;
                    bf[nt][0] = __float_as_uint(Bb[(ks * 8 + tig) * 136 + col]);
                    bf[nt][1] = __float_as_uint(Bb[(ks * 8 + tig + 4) * 136 + col]);
                }
#pragma unroll
                for (int mt = 0; mt < 2; mt++)
#pragma unroll
                    for (int nt = 0; nt < 8; nt++)
                        mma_tf32(acc[mt][nt], af[mt], bf[nt]);
            }
        }
        __syncthreads();
    }

    // epilogue: bias + tf32-round + scatter into Q/K/V [B,H,S,D]
#pragma unroll
    for (int mt = 0; mt < 2; mt++)
#pragma unroll
        for (int nt = 0; nt < 8; nt++)
#pragma unroll
            for (int half = 0; half < 2; half++) {
                const int r = rBase + wm * 32 + mt * 16 + gid + half * 8;
                const int c = cBase + wn * 64 + nt * 8 + 2 * tig;
                float2 v;
                v.x = __uint_as_float(f2tf(acc[mt][nt][half * 2 + 0] + bias[c]));
                v.y = __uint_as_float(f2tf(acc[mt][nt][half * 2 + 1] + bias[c + 1]));
                const int b_ = r >> 10, s_ = r & 1023;
                const int which = c >> 10;
                const int e = c & 1023;
                const int h = e >> 6, d = e & 63;
                float* dst = (which == 0) ? g_Q : (which == 1) ? g_K : g_V;
                *(float2*)&dst[(((size_t)(b_ * HH + h)) * SS + s_) * DD + d] = v;
            }
}

// ---------------------------------------------------------------------------
// Kernel 2: causal flash attention, tf32 mma, QT=64 (4 warps), KT=32.
// Inputs pre-rounded -> raw fragment loads. K/V cp.async double-buffered.
// ---------------------------------------------------------------------------
#define QT 64
#define KT 32
__global__ __launch_bounds__(128) void flash_attn_tc()
{
    __shared__ float Ks[2][KT][68];
    __shared__ float Vs[2][KT][72];
    __shared__ float Ps[4][16][KT + 4];

    const int tid  = threadIdx.x;
    const int lane = tid & 31;
    const int warp = tid >> 5;
    const int gid  = lane >> 2;
    const int tig  = lane & 3;
    const int bh   = blockIdx.y;
    const int q0   = blockIdx.x * QT;
    const int r0   = q0 + warp * 16 + gid;
    const int r1   = r0 + 8;

    uint32_t qa[8][4];
    {
        const float* Qb = g_Q + ((size_t)bh * SS) * DD;  // pre-rounded tf32
#pragma unroll
        for (int ks = 0; ks < 8; ks++) {   // *0.125 = exponent shift, tf32-exact
            qa[ks][0] = __float_as_uint(Qb[(size_t)r0 * DD + ks * 8 + tig] * ATT_SCALE);
            qa[ks][1] = __float_as_uint(Qb[(size_t)r1 * DD + ks * 8 + tig] * ATT_SCALE);
            qa[ks][2] = __float_as_uint(Qb[(size_t)r0 * DD + ks * 8 + tig + 4] * ATT_SCALE);
            qa[ks][3] = __float_as_uint(Qb[(size_t)r1 * DD + ks * 8 + tig + 4] * ATT_SCALE);
        }
    }

    float m0 = -1e30f, m1 = -1e30f, l0 = 0.f, l1 = 0.f;
    float oa[8][4];
#pragma unroll
    for (int i = 0; i < 8; i++)
#pragma unroll
        for (int j = 0; j < 4; j++) oa[i][j] = 0.f;

    const float* Kb = g_K + ((size_t)bh * SS) * DD;
    const float* Vb = g_V + ((size_t)bh * SS) * DD;
    const uint32_t sK = (uint32_t)__cvta_generic_to_shared(&Ks[0][0][0]);
    const uint32_t sV = (uint32_t)__cvta_generic_to_shared(&Vs[0][0][0]);
    const uint32_t stK = KT * 68 * 4;
    const uint32_t stV = KT * 72 * 4;

    auto loadTile = [&](int buf, int k0) {
#pragma unroll
        for (int i = 0; i < 4; i++) {
            const int idx = tid + i * 128;
            const int key = idx >> 4;
            const int c4  = (idx & 15) * 4;
            cp_async16(sK + buf * stK + (key * 68 + c4) * 4,
                       Kb + (size_t)(k0 + key) * DD + c4);
            cp_async16(sV + buf * stV + (key * 72 + c4) * 4,
                       Vb + (size_t)(k0 + key) * DD + c4);
        }
    };

    const int nkt = (blockIdx.x + 1) * (QT / KT);
    loadTile(0, 0);
    CP_COMMIT();

    for (int kt = 0; kt < nkt; kt++) {
        if (kt + 1 < nkt) {
            loadTile((kt + 1) & 1, (kt + 1) * KT);
            CP_COMMIT();
            CP_WAIT1();
        } else {
            CP_WAIT0();
        }
        __syncthreads();
        const float (*Kt)[68] = Ks[kt & 1];
        const float (*Vt)[72] = Vs[kt & 1];
        const int k0 = kt * KT;

        float sc[4][4];
#pragma unroll
        for (int i = 0; i < 4; i++)
#pragma unroll
            for (int j = 0; j < 4; j++) sc[i][j] = 0.f;
#pragma unroll
        for (int ks = 0; ks < 8; ks++) {
#pragma unroll
            for (int snt = 0; snt < 4; snt++) {
                uint32_t bf[2];
                bf[0] = __float_as_uint(Kt[snt * 8 + gid][ks * 8 + tig]);
                bf[1] = __float_as_uint(Kt[snt * 8 + gid][ks * 8 + tig + 4]);
                mma_tf32(sc[snt], qa[ks], bf);
            }
        }

        float mt0 = -1e30f, mt1 = -1e30f;
#pragma unroll
        for (int snt = 0; snt < 4; snt++) {
            const int c0 = k0 + snt * 8 + 2 * tig;
            if (c0 > r0)     sc[snt][0] = -1e30f;
            if (c0 + 1 > r0) sc[snt][1] = -1e30f;
            if (c0 > r1)     sc[snt][2] = -1e30f;
            if (c0 + 1 > r1) sc[snt][3] = -1e30f;
            mt0 = fmaxf(mt0, fmaxf(sc[snt][0], sc[snt][1]));
            mt1 = fmaxf(mt1, fmaxf(sc[snt][2], sc[snt][3]));
        }
        mt0 = fmaxf(mt0, __shfl_xor_sync(0xffffffffu, mt0, 1));
        mt0 = fmaxf(mt0, __shfl_xor_sync(0xffffffffu, mt0, 2));
        mt1 = fmaxf(mt1, __shfl_xor_sync(0xffffffffu, mt1, 1));
        mt1 = fmaxf(mt1, __shfl_xor_sync(0xffffffffu, mt1, 2));

        const float nm0 = fmaxf(m0, mt0);
        const float nm1 = fmaxf(m1, mt1);
        const float al0 = __expf(m0 - nm0);
        const float al1 = __expf(m1 - nm1);
        m0 = nm0; m1 = nm1;

        float s0 = 0.f, s1 = 0.f;
#pragma unroll
        for (int snt = 0; snt < 4; snt++) {
            float p0 = __expf(sc[snt][0] - nm0);
            float p1 = __expf(sc[snt][1] - nm0);
            float p2 = __expf(sc[snt][2] - nm1);
            float p3 = __expf(sc[snt][3] - nm1);
            s0 += p0 + p1; s1 += p2 + p3;
            const int col = snt * 8 + 2 * tig;
            float2 w0 = {__uint_as_float(f2tf(p0)), __uint_as_float(f2tf(p1))};
            float2 w1 = {__uint_as_float(f2tf(p2)), __uint_as_float(f2tf(p3))};
            *(float2*)&Ps[warp][gid][col] = w0;
            *(float2*)&Ps[warp][gid + 8][col] = w1;
        }
        s0 += __shfl_xor_sync(0xffffffffu, s0, 1);
        s0 += __shfl_xor_sync(0xffffffffu, s0, 2);
        s1 += __shfl_xor_sync(0xffffffffu, s1, 1);
        s1 += __shfl_xor_sync(0xffffffffu, s1, 2);
        l0 = l0 * al0 + s0;
        l1 = l1 * al1 + s1;

#pragma unroll
        for (int dnt = 0; dnt < 8; dnt++) {
            oa[dnt][0] *= al0; oa[dnt][1] *= al0;
            oa[dnt][2] *= al1; oa[dnt][3] *= al1;
        }
        __syncwarp();

#pragma unroll
        for (int ks = 0; ks < 4; ks++) {
            uint32_t af[4];
            af[0] = __float_as_uint(Ps[warp][gid][ks * 8 + tig]);
            af[1] = __float_as_uint(Ps[warp][gid + 8][ks * 8 + tig]);
            af[2] = __float_as_uint(Ps[warp][gid][ks * 8 + tig + 4]);
            af[3] = __float_as_uint(Ps[warp][gid + 8][ks * 8 + tig + 4]);
#pragma unroll
            for (int dnt = 0; dnt < 8; dnt++) {
                uint32_t bf[2];
                bf[0] = __float_as_uint(Vt[ks * 8 + tig][dnt * 8 + gid]);
                bf[1] = __float_as_uint(Vt[ks * 8 + tig + 4][dnt * 8 + gid]);
                mma_tf32(oa[dnt], af, bf);
            }
        }
        __syncthreads();
    }

    const float inv0 = 1.f / l0;
    const float inv1 = 1.f / l1;
    float* Ob = g_O + ((size_t)bh * SS) * DD;
#pragma unroll
    for (int dnt = 0; dnt < 8; dnt++) {
        const int col = dnt * 8 + 2 * tig;
        float2 v0 = {__uint_as_float(f2tf(oa[dnt][0] * inv0)),
                     __uint_as_float(f2tf(oa[dnt][1] * inv0))};
        float2 v1 = {__uint_as_float(f2tf(oa[dnt][2] * inv1)),
                     __uint_as_float(f2tf(oa[dnt][3] * inv1))};
        *(float2*)&Ob[(size_t)r0 * DD + col] = v0;
        *(float2*)&Ob[(size_t)r1 * DD + col] = v1;
    }
}

// ---------------------------------------------------------------------------
// Kernel 3: output projection (tf32 mma, pre-rounded inputs, R7 layout).
// ---------------------------------------------------------------------------
__global__ __launch_bounds__(256, 2) void out_gemm_tc(
    const float* __restrict__ bias, float* __restrict__ out)
{
    __shared__ float As[2][128 * 20];
    __shared__ float Bs[2][16 * 136];

    const int tid  = threadIdx.x;
    const int lane = tid & 31;
    const int warp = tid >> 5;
    const int wm   = warp >> 1;
    const int wn   = warp & 1;
    const int gid  = lane >> 2;
    const int tig  = lane & 3;
    const int rBase = blockIdx.y * 128;
    const int cBase = blockIdx.x * 128;

    float acc[2][8][4];
#pragma unroll
    for (int i = 0; i < 2; i++)
#pragma unroll
        for (int j = 0; j < 8; j++)
#pragma unroll
            for (int k = 0; k < 4; k++) acc[i][j][k] = 0.f;

    const int am = tid >> 2;
    const int ak = (tid & 3) * 4;
    const int kb = tid >> 5;
    const int nb = (tid & 31) * 4;

    const int r0 = rBase + am;
    const int r1 = rBase + am + 64;
    const int b0_ = r0 >> 10, s0_ = r0 & 1023;
    const int b1_ = r1 >> 10, s1_ = r1 & 1023;

    const float* Bg0 = g_Wo + (size_t)kb * EE + cBase + nb;
    const float* Bg1 = g_Wo + (size_t)(kb + 8) * EE + cBase + nb;

    const uint32_t sA = (uint32_t)__cvta_generic_to_shared(&As[0][0]);
    const uint32_t sB = (uint32_t)__cvta_generic_to_shared(&Bs[0][0]);
    const uint32_t sA0 = sA + (am * 20 + ak) * 4;
    const uint32_t sA1 = sA + ((am + 64) * 20 + ak) * 4;
    const uint32_t sB0 = sB + (kb * 136 + nb) * 4;
    const uint32_t sB1 = sB + ((kb + 8) * 136 + nb) * 4;
    const uint32_t stA = 128 * 20 * 4;
    const uint32_t stB = 16 * 136 * 4;

    auto loadTile = [&](int buf, int k0) {
        const int k = k0 + ak;
        const int h = k >> 6, d = k & 63;
        cp_async16(sA0 + buf * stA,
                   g_O + (((size_t)(b0_ * HH + h)) * SS + s0_) * DD + d);
        cp_async16(sA1 + buf * stA,
                   g_O + (((size_t)(b1_ * HH + h)) * SS + s1_) * DD + d);
        cp_async16(sB0 + buf * stB, Bg0 + (size_t)k0 * EE);
        cp_async16(sB1 + buf * stB, Bg1 + (size_t)k0 * EE);
    };

    loadTile(0, 0);
    CP_COMMIT();

    for (int it = 0; it < 64; ++it) {
        if (it + 1 < 64) {
            loadTile((it + 1) & 1, (it + 1) * 16);
            CP_COMMIT();
            CP_WAIT1();
        } else {
            CP_WAIT0();
        }
        __syncthreads();
        {
            const float* Ab = As[it & 1];
            const float* Bb = Bs[it & 1];
#pragma unroll
            for (int ks = 0; ks < 2; ks++) {
                uint32_t af[2][4];
#pragma unroll
                for (int mt = 0; mt < 2; mt++) {
                    const int base = (wm * 32 + mt * 16 + gid) * 20 + ks * 8 + tig;
                    af[mt][0] = __float_as_uint(Ab[base]);
                    af[mt][1] = __float_as_uint(Ab[base + 160]);
                    af[mt][2] = __float_as_uint(Ab[base + 4]);
                    af[mt][3] = __float_as_uint(Ab[base + 164]);
                }
                uint32_t bf[8][2];
#pragma unroll
                for (int nt = 0; nt < 8; nt++) {
                    const int col = wn * 64 + nt * 8 + gid;
                    bf[nt][0] = __float_as_uint(Bb[(ks * 8 + tig) * 136 + col]);
                    bf[nt][1] = __float_as_uint(Bb[(ks * 8 + tig + 4) * 136 + col]);
                }
#pragma unroll
                for (int mt = 0; mt < 2; mt++)
#pragma unroll
                    for (int nt = 0; nt < 8; nt++)
                        mma_tf32(acc[mt][nt], af[mt], bf[nt]);
            }
        }
        __syncthreads();
    }

#pragma unroll
    for (int mt = 0; mt < 2; mt++)
#pragma unroll
        for (int nt = 0; nt < 8; nt++)
#pragma unroll
            for (int half = 0; half < 2; half++) {
                const int r = rBase + wm * 32 + mt * 16 + gid + half * 8;
                const int c = cBase + wn * 64 + nt * 8 + 2 * tig;
                float2 v;
                v.x = acc[mt][nt][half * 2 + 0] + bias[c];
                v.y = acc[mt][nt][half * 2 + 1] + bias[c + 1];
                *(float2*)&out[(size_t)r * EE + c] = v;
            }
}

// ---------------------------------------------------------------------------
extern "C" void kernel_launch(void* const* d_in, const int* in_sizes, int n_in,
                              void* d_out, int out_size)
{
    const float* x = (const float*)d_in[0];
    const float* Wqkv = (const float*)d_in[2];
    const float* bqkv = (const float*)d_in[3];
    const float* Wo = (const float*)d_in[4];
    const float* bo = (const float*)d_in[5];
    float* out = (float*)d_out;

    float* gX;  cudaGetSymbolAddress((void**)&gX,  g_X);
    float* gWq; cudaGetSymbolAddress((void**)&gWq, g_Wq);
    float* gWo; cudaGetSymbolAddress((void**)&gWo, g_Wo);

    round_kernel<<<(BB*SS*EE/4 + 255)/256, 256>>>(x, gX, BB*SS*EE/4);
    round_kernel<<<(EE*NE3/4 + 255)/256, 256>>>(Wqkv, gWq, EE*NE3/4);
    round_kernel<<<(EE*EE/4 + 255)/256, 256>>>(Wo, gWo, EE*EE/4);
    {
        dim3 grid(NE3 / 128, (BB * SS) / 128);   // (24, 32)
        qkv_gemm_tc<<<grid, 256>>>(bqkv);
    }
    {
        dim3 grid(SS / QT, BB * HH);             // (16, 64)
        flash_attn_tc<<<grid, 128>>>();
    }
    {
        dim3 grid(EE / 128, (BB * SS) / 128);    // (8, 32)
        out_gemm_tc<<<grid, 256>>>(bo, out);
    }
}

// round 10
// speedup vs baseline: 1.3200x; 1.0562x over previous
#include <cuda_runtime.h>
#include <cstdint>

#define BB 4
#define SS 1024
#define EE 1024
#define HH 16
#define DD 64
#define NE3 3072
static constexpr float ATT_SCALE = 0.125f; // 1/sqrt(64), exact in tf32

// GEMM smem: A 2 stages of 128x36 f32, B 2 stages of 32x136 f32
#define GEMM_SMEM_BYTES ((2 * 128 * 36 + 2 * 32 * 136) * 4)   // 71680

// Scratch (no allocations allowed)
__device__ float g_Q[BB*HH*SS*DD];
__device__ float g_K[BB*HH*SS*DD];
__device__ float g_V[BB*HH*SS*DD];
__device__ float g_O[BB*HH*SS*DD];
__device__ float g_X[BB*SS*EE];     // tf32-rounded X
__device__ float g_Wq[EE*NE3];      // tf32-rounded Wqkv ([k][n] layout)
__device__ float g_Wo[EE*EE];       // tf32-rounded Wo

// f32 -> tf32 round-to-nearest
__device__ __forceinline__ uint32_t f2tf(float x) {
    uint32_t r;
    asm("cvt.rna.tf32.f32 %0, %1;" : "=r"(r) : "f"(x));
    return r;
}

__device__ __forceinline__ void mma_tf32(float* c, const uint32_t* a, const uint32_t* b) {
    asm volatile(
        "mma.sync.aligned.m16n8k8.row.col.f32.tf32.tf32.f32 "
        "{%0,%1,%2,%3},{%4,%5,%6,%7},{%8,%9},{%0,%1,%2,%3};"
        : "+f"(c[0]), "+f"(c[1]), "+f"(c[2]), "+f"(c[3])
        : "r"(a[0]), "r"(a[1]), "r"(a[2]), "r"(a[3]), "r"(b[0]), "r"(b[1]));
}

__device__ __forceinline__ void cp_async16(uint32_t saddr, const void* gaddr) {
    asm volatile("cp.async.cg.shared.global [%0], [%1], 16;"
                 :: "r"(saddr), "l"(gaddr));
}
#define CP_COMMIT() asm volatile("cp.async.commit_group;")
#define CP_WAIT1()  asm volatile("cp.async.wait_group 1;")
#define CP_WAIT0()  asm volatile("cp.async.wait_group 0;")

// ---------------------------------------------------------------------------
// Pre-pass: elementwise tf32-round (coalesced).
// ---------------------------------------------------------------------------
__global__ __launch_bounds__(256) void round_kernel(
    const float* __restrict__ in, float* __restrict__ out, int n4)
{
    int i = blockIdx.x * blockDim.x + threadIdx.x;
    if (i < n4) {
        float4 v = ((const float4*)in)[i];
        uint4 r = {f2tf(v.x), f2tf(v.y), f2tf(v.z), f2tf(v.w)};
        ((uint4*)out)[i] = r;
    }
}

// ---------------------------------------------------------------------------
// GEMM geometry: block 128x128, BK=32, 8 warps (4m x 2n), warp tile 32x64.
// Dynamic smem (pre-rounded f32): A [m][k] stride 36, B [k][n] stride 136.
// 64 MMAs between barrier pairs (2x the R9 density). 2 CTAs/SM.
// Pipeline: issue loads(it+1) -> commit -> WAIT1 -> sync -> compute -> sync.
// ---------------------------------------------------------------------------

// Kernel 1: QKV GEMM -> scatter to g_Q/K/V (tf32-rounded at store)
__global__ __launch_bounds__(256, 2) void qkv_gemm_tc(
    const float* __restrict__ bias)
{
    extern __shared__ float dyn[];
    // layout (floats): A stage0 @0, A stage1 @4608, B stage0 @9216, B stage1 @13568
    const int tid  = threadIdx.x;
    const int lane = tid & 31;
    const int warp = tid >> 5;
    const int wm   = warp >> 1;
    const int wn   = warp & 1;
    const int gid  = lane >> 2;
    const int tig  = lane & 3;
    const int rBase = blockIdx.y * 128;
    const int cBase = blockIdx.x * 128;

    float acc[2][8][4];
#pragma unroll
    for (int i = 0; i < 2; i++)
#pragma unroll
        for (int j = 0; j < 8; j++)
#pragma unroll
            for (int k = 0; k < 4; k++) acc[i][j][k] = 0.f;

    const uint32_t sBase = (uint32_t)__cvta_generic_to_shared(dyn);
    const uint32_t stA = 128 * 36 * 4;          // 18432 B
    const uint32_t stB = 32 * 136 * 4;          // 17408 B
    const uint32_t bOff = 2 * stA;              // B region start

    // cp.async mapping: A 1024 chunks (128 rows x 8), B 1024 chunks (32 rows x 32)
    auto loadTile = [&](int buf, int k0) {
#pragma unroll
        for (int i = 0; i < 4; i++) {
            const int ia  = tid + i * 256;
            const int ar  = ia >> 3;            // 0..127
            const int ac4 = (ia & 7) * 4;       // 0..28
            cp_async16(sBase + buf * stA + (ar * 36 + ac4) * 4,
                       g_X + (size_t)(rBase + ar) * EE + k0 + ac4);
            const int kr  = ia >> 5;            // 0..31
            const int nc  = (ia & 31) * 4;      // 0..124
            cp_async16(sBase + bOff + buf * stB + (kr * 136 + nc) * 4,
                       g_Wq + (size_t)(k0 + kr) * NE3 + cBase + nc);
        }
    };

    loadTile(0, 0);
    CP_COMMIT();

    for (int it = 0; it < 32; ++it) {
        if (it + 1 < 32) {
            loadTile((it + 1) & 1, (it + 1) * 32);
            CP_COMMIT();
            CP_WAIT1();
        } else {
            CP_WAIT0();
        }
        __syncthreads();
        {
            const float* Ab = dyn + (it & 1) * (128 * 36);
            const float* Bb = dyn + 2 * (128 * 36) + (it & 1) * (32 * 136);
#pragma unroll
            for (int ks = 0; ks < 4; ks++) {
                uint32_t af[2][4];
#pragma unroll
                for (int mt = 0; mt < 2; mt++) {
                    const int base = (wm * 32 + mt * 16 + gid) * 36 + ks * 8 + tig;
                    af[mt][0] = __float_as_uint(Ab[base]);
                    af[mt][1] = __float_as_uint(Ab[base + 288]);   // +8 rows
                    af[mt][2] = __float_as_uint(Ab[base + 4]);
                    af[mt][3] = __float_as_uint(Ab[base + 292]);
                }
                uint32_t bf[8][2];
#pragma unroll
                for (int nt = 0; nt < 8; nt++) {
                    const int col = wn * 64 + nt * 8 + gid;
                    bf[nt][0] = __float_as_uint(Bb[(ks * 8 + tig) * 136 + col]);
                    bf[nt][1] = __float_as_uint(Bb[(ks * 8 + tig + 4) * 136 + col]);
                }
#pragma unroll
                for (int mt = 0; mt < 2; mt++)
#pragma unroll
                    for (int nt = 0; nt < 8; nt++)
                        mma_tf32(acc[mt][nt], af[mt], bf[nt]);
            }
        }
        __syncthreads();
    }

    // epilogue: bias + tf32-round + scatter into Q/K/V [B,H,S,D]
#pragma unroll
    for (int mt = 0; mt < 2; mt++)
#pragma unroll
        for (int nt = 0; nt < 8; nt++)
#pragma unroll
            for (int half = 0; half < 2; half++) {
                const int r = rBase + wm * 32 + mt * 16 + gid + half * 8;
                const int c = cBase + wn * 64 + nt * 8 + 2 * tig;
                float2 v;
                v.x = __uint_as_float(f2tf(acc[mt][nt][half * 2 + 0] + bias[c]));
                v.y = __uint_as_float(f2tf(acc[mt][nt][half * 2 + 1] + bias[c + 1]));
                const int b_ = r >> 10, s_ = r & 1023;
                const int which = c >> 10;
                const int e = c & 1023;
                const int h = e >> 6, d = e & 63;
                float* dst = (which == 0) ? g_Q : (which == 1) ? g_K : g_V;
                *(float2*)&dst[(((size_t)(b_ * HH + h)) * SS + s_) * DD + d] = v;
            }
}

// ---------------------------------------------------------------------------
// Kernel 2: causal flash attention (unchanged R9: tf32 mma, QT=64, KT=32,
// pre-rounded inputs, cp.async double-buffered K/V).
// ---------------------------------------------------------------------------
#define QT 64
#define KT 32
__global__ __launch_bounds__(128) void flash_attn_tc()
{
    __shared__ float Ks[2][KT][68];
    __shared__ float Vs[2][KT][72];
    __shared__ float Ps[4][16][KT + 4];

    const int tid  = threadIdx.x;
    const int lane = tid & 31;
    const int warp = tid >> 5;
    const int gid  = lane >> 2;
    const int tig  = lane & 3;
    const int bh   = blockIdx.y;
    const int q0   = blockIdx.x * QT;
    const int r0   = q0 + warp * 16 + gid;
    const int r1   = r0 + 8;

    uint32_t qa[8][4];
    {
        const float* Qb = g_Q + ((size_t)bh * SS) * DD;
#pragma unroll
        for (int ks = 0; ks < 8; ks++) {
            qa[ks][0] = __float_as_uint(Qb[(size_t)r0 * DD + ks * 8 + tig] * ATT_SCALE);
            qa[ks][1] = __float_as_uint(Qb[(size_t)r1 * DD + ks * 8 + tig] * ATT_SCALE);
            qa[ks][2] = __float_as_uint(Qb[(size_t)r0 * DD + ks * 8 + tig + 4] * ATT_SCALE);
            qa[ks][3] = __float_as_uint(Qb[(size_t)r1 * DD + ks * 8 + tig + 4] * ATT_SCALE);
        }
    }

    float m0 = -1e30f, m1 = -1e30f, l0 = 0.f, l1 = 0.f;
    float oa[8][4];
#pragma unroll
    for (int i = 0; i < 8; i++)
#pragma unroll
        for (int j = 0; j < 4; j++) oa[i][j] = 0.f;

    const float* Kb = g_K + ((size_t)bh * SS) * DD;
    const float* Vb = g_V + ((size_t)bh * SS) * DD;
    const uint32_t sK = (uint32_t)__cvta_generic_to_shared(&Ks[0][0][0]);
    const uint32_t sV = (uint32_t)__cvta_generic_to_shared(&Vs[0][0][0]);
    const uint32_t stK = KT * 68 * 4;
    const uint32_t stV = KT * 72 * 4;

    auto loadTile = [&](int buf, int k0) {
#pragma unroll
        for (int i = 0; i < 4; i++) {
            const int idx = tid + i * 128;
            const int key = idx >> 4;
            const int c4  = (idx & 15) * 4;
            cp_async16(sK + buf * stK + (key * 68 + c4) * 4,
                       Kb + (size_t)(k0 + key) * DD + c4);
            cp_async16(sV + buf * stV + (key * 72 + c4) * 4,
                       Vb + (size_t)(k0 + key) * DD + c4);
        }
    };

    const int nkt = (blockIdx.x + 1) * (QT / KT);
    loadTile(0, 0);
    CP_COMMIT();

    for (int kt = 0; kt < nkt; kt++) {
        if (kt + 1 < nkt) {
            loadTile((kt + 1) & 1, (kt + 1) * KT);
            CP_COMMIT();
            CP_WAIT1();
        } else {
            CP_WAIT0();
        }
        __syncthreads();
        const float (*Kt)[68] = Ks[kt & 1];
        const float (*Vt)[72] = Vs[kt & 1];
        const int k0 = kt * KT;

        float sc[4][4];
#pragma unroll
        for (int i = 0; i < 4; i++)
#pragma unroll
            for (int j = 0; j < 4; j++) sc[i][j] = 0.f;
#pragma unroll
        for (int ks = 0; ks < 8; ks++) {
#pragma unroll
            for (int snt = 0; snt < 4; snt++) {
                uint32_t bf[2];
                bf[0] = __float_as_uint(Kt[snt * 8 + gid][ks * 8 + tig]);
                bf[1] = __float_as_uint(Kt[snt * 8 + gid][ks * 8 + tig + 4]);
                mma_tf32(sc[snt], qa[ks], bf);
            }
        }

        float mt0 = -1e30f, mt1 = -1e30f;
#pragma unroll
        for (int snt = 0; snt < 4; snt++) {
            const int c0 = k0 + snt * 8 + 2 * tig;
            if (c0 > r0)     sc[snt][0] = -1e30f;
            if (c0 + 1 > r0) sc[snt][1] = -1e30f;
            if (c0 > r1)     sc[snt][2] = -1e30f;
            if (c0 + 1 > r1) sc[snt][3] = -1e30f;
            mt0 = fmaxf(mt0, fmaxf(sc[snt][0], sc[snt][1]));
            mt1 = fmaxf(mt1, fmaxf(sc[snt][2], sc[snt][3]));
        }
        mt0 = fmaxf(mt0, __shfl_xor_sync(0xffffffffu, mt0, 1));
        mt0 = fmaxf(mt0, __shfl_xor_sync(0xffffffffu, mt0, 2));
        mt1 = fmaxf(mt1, __shfl_xor_sync(0xffffffffu, mt1, 1));
        mt1 = fmaxf(mt1, __shfl_xor_sync(0xffffffffu, mt1, 2));

        const float nm0 = fmaxf(m0, mt0);
        const float nm1 = fmaxf(m1, mt1);
        const float al0 = __expf(m0 - nm0);
        const float al1 = __expf(m1 - nm1);
        m0 = nm0; m1 = nm1;

        float s0 = 0.f, s1 = 0.f;
#pragma unroll
        for (int snt = 0; snt < 4; snt++) {
            float p0 = __expf(sc[snt][0] - nm0);
            float p1 = __expf(sc[snt][1] - nm0);
            float p2 = __expf(sc[snt][2] - nm1);
            float p3 = __expf(sc[snt][3] - nm1);
            s0 += p0 + p1; s1 += p2 + p3;
            const int col = snt * 8 + 2 * tig;
            float2 w0 = {__uint_as_float(f2tf(p0)), __uint_as_float(f2tf(p1))};
            float2 w1 = {__uint_as_float(f2tf(p2)), __uint_as_float(f2tf(p3))};
            *(float2*)&Ps[warp][gid][col] = w0;
            *(float2*)&Ps[warp][gid + 8][col] = w1;
        }
        s0 += __shfl_xor_sync(0xffffffffu, s0, 1);
        s0 += __shfl_xor_sync(0xffffffffu, s0, 2);
        s1 += __shfl_xor_sync(0xffffffffu, s1, 1);
        s1 += __shfl_xor_sync(0xffffffffu, s1, 2);
        l0 = l0 * al0 + s0;
        l1 = l1 * al1 + s1;

#pragma unroll
        for (int dnt = 0; dnt < 8; dnt++) {
            oa[dnt][0] *= al0; oa[dnt][1] *= al0;
            oa[dnt][2] *= al1; oa[dnt][3] *= al1;
        }
        __syncwarp();

#pragma unroll
        for (int ks = 0; ks < 4; ks++) {
            uint32_t af[4];
            af[0] = __float_as_uint(Ps[warp][gid][ks * 8 + tig]);
            af[1] = __float_as_uint(Ps[warp][gid + 8][ks * 8 + tig]);
            af[2] = __float_as_uint(Ps[warp][gid][ks * 8 + tig + 4]);
            af[3] = __float_as_uint(Ps[warp][gid + 8][ks * 8 + tig + 4]);
#pragma unroll
            for (int dnt = 0; dnt < 8; dnt++) {
                uint32_t bf[2];
                bf[0] = __float_as_uint(Vt[ks * 8 + tig][dnt * 8 + gid]);
                bf[1] = __float_as_uint(Vt[ks * 8 + tig + 4][dnt * 8 + gid]);
                mma_tf32(oa[dnt], af, bf);
            }
        }
        __syncthreads();
    }

    const float inv0 = 1.f / l0;
    const float inv1 = 1.f / l1;
    float* Ob = g_O + ((size_t)bh * SS) * DD;
#pragma unroll
    for (int dnt = 0; dnt < 8; dnt++) {
        const int col = dnt * 8 + 2 * tig;
        float2 v0 = {__uint_as_float(f2tf(oa[dnt][0] * inv0)),
                     __uint_as_float(f2tf(oa[dnt][1] * inv0))};
        float2 v1 = {__uint_as_float(f2tf(oa[dnt][2] * inv1)),
                     __uint_as_float(f2tf(oa[dnt][3] * inv1))};
        *(float2*)&Ob[(size_t)r0 * DD + col] = v0;
        *(float2*)&Ob[(size_t)r1 * DD + col] = v1;
    }
}

// ---------------------------------------------------------------------------
// Kernel 3: output projection (tf32 mma, BK=32, dynamic smem).
// A gathered from g_O [B,H,S,D] (4-float chunks never cross head boundary).
// ---------------------------------------------------------------------------
__global__ __launch_bounds__(256, 2) void out_gemm_tc(
    const float* __restrict__ bias, float* __restrict__ out)
{
    extern __shared__ float dyn[];
    const int tid  = threadIdx.x;
    const int lane = tid & 31;
    const int warp = tid >> 5;
    const int wm   = warp >> 1;
    const int wn   = warp & 1;
    const int gid  = lane >> 2;
    const int tig  = lane & 3;
    const int rBase = blockIdx.y * 128;
    const int cBase = blockIdx.x * 128;

    float acc[2][8][4];
#pragma unroll
    for (int i = 0; i < 2; i++)
#pragma unroll
        for (int j = 0; j < 8; j++)
#pragma unroll
            for (int k = 0; k < 4; k++) acc[i][j][k] = 0.f;

    const uint32_t sBase = (uint32_t)__cvta_generic_to_shared(dyn);
    const uint32_t stA = 128 * 36 * 4;
    const uint32_t stB = 32 * 136 * 4;
    const uint32_t bOff = 2 * stA;

    auto loadTile = [&](int buf, int k0) {
#pragma unroll
        for (int i = 0; i < 4; i++) {
            const int ia  = tid + i * 256;
            const int ar  = ia >> 3;
            const int ac4 = (ia & 7) * 4;
            const int r   = rBase + ar;
            const int b_  = r >> 10, s_ = r & 1023;
            const int k   = k0 + ac4;
            const int h   = k >> 6, d = k & 63;
            cp_async16(sBase + buf * stA + (ar * 36 + ac4) * 4,
                       g_O + (((size_t)(b_ * HH + h)) * SS + s_) * DD + d);
            const int kr  = ia >> 5;
            const int nc  = (ia & 31) * 4;
            cp_async16(sBase + bOff + buf * stB + (kr * 136 + nc) * 4,
                       g_Wo + (size_t)(k0 + kr) * EE + cBase + nc);
        }
    };

    loadTile(0, 0);
    CP_COMMIT();

    for (int it = 0; it < 32; ++it) {
        if (it + 1 < 32) {
            loadTile((it + 1) & 1, (it + 1) * 32);
            CP_COMMIT();
            CP_WAIT1();
        } else {
            CP_WAIT0();
        }
        __syncthreads();
        {
            const float* Ab = dyn + (it & 1) * (128 * 36);
            const float* Bb = dyn + 2 * (128 * 36) + (it & 1) * (32 * 136);
#pragma unroll
            for (int ks = 0; ks < 4; ks++) {
                uint32_t af[2][4];
#pragma unroll
                for (int mt = 0; mt < 2; mt++) {
                    const int base = (wm * 32 + mt * 16 + gid) * 36 + ks * 8 + tig;
                    af[mt][0] = __float_as_uint(Ab[base]);
                    af[mt][1] = __float_as_uint(Ab[base + 288]);
                    af[mt][2] = __float_as_uint(Ab[base + 4]);
                    af[mt][3] = __float_as_uint(Ab[base + 292]);
                }
                uint32_t bf[8][2];
#pragma unroll
                for (int nt = 0; nt < 8; nt++) {
                    const int col = wn * 64 + nt * 8 + gid;
                    bf[nt][0] = __float_as_uint(Bb[(ks * 8 + tig) * 136 + col]);
                    bf[nt][1] = __float_as_uint(Bb[(ks * 8 + tig + 4) * 136 + col]);
                }
#pragma unroll
                for (int mt = 0; mt < 2; mt++)
#pragma unroll
                    for (int nt = 0; nt < 8; nt++)
                        mma_tf32(acc[mt][nt], af[mt], bf[nt]);
            }
        }
        __syncthreads();
    }

#pragma unroll
    for (int mt = 0; mt < 2; mt++)
#pragma unroll
        for (int nt = 0; nt < 8; nt++)
#pragma unroll
            for (int half = 0; half < 2; half++) {
                const int r = rBase + wm * 32 + mt * 16 + gid + half * 8;
                const int c = cBase + wn * 64 + nt * 8 + 2 * tig;
                float2 v;
                v.x = acc[mt][nt][half * 2 + 0] + bias[c];
                v.y = acc[mt][nt][half * 2 + 1] + bias[c + 1];
                *(float2*)&out[(size_t)r * EE + c] = v;
            }
}

// ---------------------------------------------------------------------------
extern "C" void kernel_launch(void* const* d_in, const int* in_sizes, int n_in,
                              void* d_out, int out_size)
{
    const float* x = (const float*)d_in[0];
    const float* Wqkv = (const float*)d_in[2];
    const float* bqkv = (const float*)d_in[3];
    const float* Wo = (const float*)d_in[4];
    const float* bo = (const float*)d_in[5];
    float* out = (float*)d_out;

    float* gX;  cudaGetSymbolAddress((void**)&gX,  g_X);
    float* gWq; cudaGetSymbolAddress((void**)&gWq, g_Wq);
    float* gWo; cudaGetSymbolAddress((void**)&gWo, g_Wo);

    // opt-in to >48KB dynamic smem (config call, not an allocation;
    // executed immediately, deterministic — capture-safe)
    cudaFuncSetAttribute(qkv_gemm_tc,
        cudaFuncAttributeMaxDynamicSharedMemorySize, GEMM_SMEM_BYTES);
    cudaFuncSetAttribute(out_gemm_tc,
        cudaFuncAttributeMaxDynamicSharedMemorySize, GEMM_SMEM_BYTES);

    round_kernel<<<(BB*SS*EE/4 + 255)/256, 256>>>(x, gX, BB*SS*EE/4);
    round_kernel<<<(EE*NE3/4 + 255)/256, 256>>>(Wqkv, gWq, EE*NE3/4);
    round_kernel<<<(EE*EE/4 + 255)/256, 256>>>(Wo, gWo, EE*EE/4);
    {
        dim3 grid(NE3 / 128, (BB * SS) / 128);   // (24, 32)
        qkv_gemm_tc<<<grid, 256, GEMM_SMEM_BYTES>>>(bqkv);
    }
    {
        dim3 grid(SS / QT, BB * HH);             // (16, 64)
        flash_attn_tc<<<grid, 128>>>();
    }
    {
        dim3 grid(EE / 128, (BB * SS) / 128);    // (8, 32)
        out_gemm_tc<<<grid, 256, GEMM_SMEM_BYTES>>>(bo, out);
    }
}

// round 12
// speedup vs baseline: 2.2565x; 1.7095x over previous
#include <cuda_runtime.h>
#include <cuda_fp16.h>
#include <cstdint>
#include <cstring>

#define BB 4
#define SS 1024
#define EE 1024
#define HH 16
#define DD 64
#define NE3 3072

// GEMM smem: A 2 stages 128x64 half (stride 72 halves), B 2 stages 32x128 half2 (stride 136)
#define GEMM_SMEM_BYTES ((2 * 128 * 36 + 2 * 32 * 136) * 4)   // 71680 (same words as R10)

// Scratch (no allocations allowed) — fp16 activations, packed fp16 weights
__device__ __half   g_Q[BB*HH*SS*DD];
__device__ __half   g_K[BB*HH*SS*DD];
__device__ uint32_t g_Vp[BB*HH*(SS/2)*DD];   // [bh][key/2][d] = half2(V[2k2][d],V[2k2+1][d])
__device__ __half   g_O[BB*HH*SS*DD];
__device__ __half   g_X[BB*SS*EE];
__device__ uint32_t g_WqP[(EE/2)*NE3];       // [k2][n] = half2(W[2k2][n],W[2k2+1][n])
__device__ uint32_t g_WoP[(EE/2)*EE];

// bit-cast helpers (the "__half2_as_uint" intrinsic does not exist)
__device__ __forceinline__ uint32_t h2u(__half2 h) {
    uint32_t u; memcpy(&u, &h, 4); return u;
}
__device__ __forceinline__ __half2 u2h(uint32_t u) {
    __half2 h; memcpy(&h, &u, 4); return h;
}

__device__ __forceinline__ void mma_f16(float* c, const uint32_t* a, const uint32_t* b) {
    asm volatile(
        "mma.sync.aligned.m16n8k16.row.col.f32.f16.f16.f32 "
        "{%0,%1,%2,%3},{%4,%5,%6,%7},{%8,%9},{%0,%1,%2,%3};"
        : "+f"(c[0]), "+f"(c[1]), "+f"(c[2]), "+f"(c[3])
        : "r"(a[0]), "r"(a[1]), "r"(a[2]), "r"(a[3]), "r"(b[0]), "r"(b[1]));
}

__device__ __forceinline__ void cp_async16(uint32_t saddr, const void* gaddr) {
    asm volatile("cp.async.cg.shared.global [%0], [%1], 16;"
                 :: "r"(saddr), "l"(gaddr));
}
#define CP_COMMIT() asm volatile("cp.async.commit_group;")
#define CP_WAIT1()  asm volatile("cp.async.wait_group 1;")
#define CP_WAIT0()  asm volatile("cp.async.wait_group 0;")

// ---------------------------------------------------------------------------
// Pre-pass kernels
// ---------------------------------------------------------------------------
__global__ __launch_bounds__(256) void x2h_kernel(
    const float* __restrict__ in, __half* __restrict__ out, int n4)
{
    int i = blockIdx.x * blockDim.x + threadIdx.x;
    if (i < n4) {
        float4 v = ((const float4*)in)[i];
        uint2 r;
        r.x = h2u(__floats2half2_rn(v.x, v.y));
        r.y = h2u(__floats2half2_rn(v.z, v.w));
        ((uint2*)out)[i] = r;
    }
}

// pack W [K][N] f32 -> out [K/2][N] half2 of k-pairs
__global__ __launch_bounds__(256) void packw_kernel(
    const float* __restrict__ in, uint32_t* __restrict__ out, int K, int N)
{
    int i = blockIdx.x * blockDim.x + threadIdx.x;   // over (K/2)*(N/4)
    int total = (K / 2) * (N / 4);
    if (i < total) {
        int k2 = i / (N / 4);
        int n  = (i % (N / 4)) * 4;
        float4 a = *(const float4*)(in + (size_t)(2 * k2) * N + n);
        float4 b = *(const float4*)(in + (size_t)(2 * k2 + 1) * N + n);
        uint4 r;
        r.x = h2u(__floats2half2_rn(a.x, b.x));
        r.y = h2u(__floats2half2_rn(a.y, b.y));
        r.z = h2u(__floats2half2_rn(a.z, b.z));
        r.w = h2u(__floats2half2_rn(a.w, b.w));
        *(uint4*)(out + (size_t)k2 * N + n) = r;
    }
}

// ---------------------------------------------------------------------------
// GEMM: block 128x128, BK=64 (fp16), 8 warps (4m x 2n), warp tile 32x64,
// m16n8k16 f16 mma (fp32 accum). 64 MMAs per barrier pair, 16 iters.
// Dyn smem: A [128 rows][72 halves] (36 words/row), B [32 k2-rows][136 half2].
// Inner-loop word indices identical to the R10-proven tf32 code.
// ---------------------------------------------------------------------------
__global__ __launch_bounds__(256, 2) void qkv_gemm_tc(
    const float* __restrict__ bias)
{
    extern __shared__ float dyn[];
    const int tid  = threadIdx.x;
    const int lane = tid & 31;
    const int warp = tid >> 5;
    const int wm   = warp >> 1;
    const int wn   = warp & 1;
    const int gid  = lane >> 2;
    const int tig  = lane & 3;
    const int rBase = blockIdx.y * 128;
    const int cBase = blockIdx.x * 128;

    float acc[2][8][4];
#pragma unroll
    for (int i = 0; i < 2; i++)
#pragma unroll
        for (int j = 0; j < 8; j++)
#pragma unroll
            for (int k = 0; k < 4; k++) acc[i][j][k] = 0.f;

    const uint32_t sBase = (uint32_t)__cvta_generic_to_shared(dyn);
    const uint32_t stA = 128 * 36 * 4;
    const uint32_t stB = 32 * 136 * 4;
    const uint32_t bOff = 2 * stA;

    auto loadTile = [&](int buf, int it) {
        const int k0  = it * 64;    // halves
        const int k20 = it * 32;    // half2 rows
#pragma unroll
        for (int i = 0; i < 4; i++) {
            const int ia  = tid + i * 256;
            const int ar  = ia >> 3;            // 0..127
            const int ac8 = (ia & 7) * 8;       // halves 0..56
            cp_async16(sBase + buf * stA + (ar * 36 + (ia & 7) * 4) * 4,
                       g_X + (size_t)(rBase + ar) * EE + k0 + ac8);
            const int kr  = ia >> 5;            // 0..31
            const int nc  = (ia & 31) * 4;      // half2 cols 0..124
            cp_async16(sBase + bOff + buf * stB + (kr * 136 + nc) * 4,
                       g_WqP + (size_t)(k20 + kr) * NE3 + cBase + nc);
        }
    };

    loadTile(0, 0);
    CP_COMMIT();

    for (int it = 0; it < 16; ++it) {
        if (it + 1 < 16) {
            loadTile((it + 1) & 1, it + 1);
            CP_COMMIT();
            CP_WAIT1();
        } else {
            CP_WAIT0();
        }
        __syncthreads();
        {
            const uint32_t* Ab = (const uint32_t*)dyn + (it & 1) * (128 * 36);
            const uint32_t* Bb = (const uint32_t*)dyn + 2 * (128 * 36) + (it & 1) * (32 * 136);
#pragma unroll
            for (int ks = 0; ks < 4; ks++) {
                uint32_t af[2][4];
#pragma unroll
                for (int mt = 0; mt < 2; mt++) {
                    const int base = (wm * 32 + mt * 16 + gid) * 36 + ks * 8 + tig;
                    af[mt][0] = Ab[base];
                    af[mt][1] = Ab[base + 288];
                    af[mt][2] = Ab[base + 4];
                    af[mt][3] = Ab[base + 292];
                }
                uint32_t bf[8][2];
#pragma unroll
                for (int nt = 0; nt < 8; nt++) {
                    const int col = wn * 64 + nt * 8 + gid;
                    bf[nt][0] = Bb[(ks * 8 + tig) * 136 + col];
                    bf[nt][1] = Bb[(ks * 8 + tig + 4) * 136 + col];
                }
#pragma unroll
                for (int mt = 0; mt < 2; mt++)
#pragma unroll
                    for (int nt = 0; nt < 8; nt++)
                        mma_f16(acc[mt][nt], af[mt], bf[nt]);
            }
        }
        __syncthreads();
    }

    // epilogue: bias (fp32) -> fp16, scatter to Q/K (half2) and Vp (packed)
#pragma unroll
    for (int mt = 0; mt < 2; mt++)
#pragma unroll
        for (int nt = 0; nt < 8; nt++)
#pragma unroll
            for (int half_ = 0; half_ < 2; half_++) {
                const int r = rBase + wm * 32 + mt * 16 + gid + half_ * 8;
                const int c = cBase + wn * 64 + nt * 8 + 2 * tig;
                float vx = acc[mt][nt][half_ * 2 + 0] + bias[c];
                float vy = acc[mt][nt][half_ * 2 + 1] + bias[c + 1];
                const int b_ = r >> 10, s_ = r & 1023;
                const int which = c >> 10;
                const int e = c & 1023;
                const int h = e >> 6, d = e & 63;
                const int bh = b_ * HH + h;
                if (which == 2) {
                    __half* vp = (__half*)g_Vp;
                    size_t base = (((size_t)bh * (SS/2) + (s_ >> 1)) * DD + d) * 2 + (s_ & 1);
                    vp[base]     = __float2half_rn(vx);
                    vp[base + 2] = __float2half_rn(vy);
                } else {
                    __half* dst = (which == 0) ? g_Q : g_K;
                    *(uint32_t*)&dst[((size_t)bh * SS + s_) * DD + d] =
                        h2u(__floats2half2_rn(vx, vy));
                }
            }
}

// ---------------------------------------------------------------------------
// Flash attention fp16: QT=64 (4 warps), KT=32, m16n8k16, fp32 softmax.
// K smem [key][72 halves]; V smem [key2][68 half2]; Ps [16][40 halves]/warp.
// All fragment loads: single 32-bit LDS, conflict-free.
// ---------------------------------------------------------------------------
#define QT 64
#define KT 32
__global__ __launch_bounds__(128) void flash_attn_tc()
{
    __shared__ __half   Ks[2][KT][72];
    __shared__ uint32_t Vs[2][16][68];
    __shared__ __half   Ps[4][16][40];

    const int tid  = threadIdx.x;
    const int lane = tid & 31;
    const int warp = tid >> 5;
    const int gid  = lane >> 2;
    const int tig  = lane & 3;
    const int bh   = blockIdx.y;
    const int q0   = blockIdx.x * QT;
    const int r0   = q0 + warp * 16 + gid;
    const int r1   = r0 + 8;

    // Q fragments, scaled by 0.125 (exponent-only, fp16-exact)
    uint32_t qa[4][4];
    {
        const __half* Qb = g_Q + ((size_t)bh * SS) * DD;
        const __half2 sc2 = __floats2half2_rn(0.125f, 0.125f);
#pragma unroll
        for (int ks = 0; ks < 4; ks++) {
            uint32_t u0 = *(const uint32_t*)&Qb[(size_t)r0 * DD + ks * 16 + 2 * tig];
            uint32_t u1 = *(const uint32_t*)&Qb[(size_t)r1 * DD + ks * 16 + 2 * tig];
            uint32_t u2 = *(const uint32_t*)&Qb[(size_t)r0 * DD + ks * 16 + 2 * tig + 8];
            uint32_t u3 = *(const uint32_t*)&Qb[(size_t)r1 * DD + ks * 16 + 2 * tig + 8];
            qa[ks][0] = h2u(__hmul2(u2h(u0), sc2));
            qa[ks][1] = h2u(__hmul2(u2h(u1), sc2));
            qa[ks][2] = h2u(__hmul2(u2h(u2), sc2));
            qa[ks][3] = h2u(__hmul2(u2h(u3), sc2));
        }
    }

    float m0 = -1e30f, m1 = -1e30f, l0 = 0.f, l1 = 0.f;
    float oa[8][4];
#pragma unroll
    for (int i = 0; i < 8; i++)
#pragma unroll
        for (int j = 0; j < 4; j++) oa[i][j] = 0.f;

    const __half* Kb = g_K + ((size_t)bh * SS) * DD;
    const uint32_t* Vb = g_Vp + (size_t)bh * (SS/2) * DD;
    const uint32_t sK = (uint32_t)__cvta_generic_to_shared(&Ks[0][0][0]);
    const uint32_t sV = (uint32_t)__cvta_generic_to_shared(&Vs[0][0][0]);
    const uint32_t stK = KT * 72 * 2;
    const uint32_t stV = 16 * 68 * 4;

    auto loadTile = [&](int buf, int k0) {
#pragma unroll
        for (int i = 0; i < 2; i++) {
            const int idx = tid + i * 128;          // 0..255
            const int key = idx >> 3;               // 0..31
            const int c8  = (idx & 7) * 8;          // halves
            cp_async16(sK + buf * stK + (key * 72 + c8) * 2,
                       Kb + (size_t)(k0 + key) * DD + c8);
            const int k2  = idx >> 4;               // 0..15
            const int c4  = (idx & 15) * 4;         // half2 units
            cp_async16(sV + buf * stV + (k2 * 68 + c4) * 4,
                       Vb + (size_t)(k0 / 2 + k2) * DD + c4);
        }
    };

    const int nkt = (blockIdx.x + 1) * (QT / KT);
    loadTile(0, 0);
    CP_COMMIT();

    for (int kt = 0; kt < nkt; kt++) {
        if (kt + 1 < nkt) {
            loadTile((kt + 1) & 1, (kt + 1) * KT);
            CP_COMMIT();
            CP_WAIT1();
        } else {
            CP_WAIT0();
        }
        __syncthreads();
        const uint32_t* KtU = (const uint32_t*)&Ks[kt & 1][0][0];
        const uint32_t* VtU = &Vs[kt & 1][0][0];
        const int k0 = kt * KT;

        // S = (Q*scale) @ K^T : 4 ks x 4 snt MMAs
        float sc[4][4];
#pragma unroll
        for (int i = 0; i < 4; i++)
#pragma unroll
            for (int j = 0; j < 4; j++) sc[i][j] = 0.f;
#pragma unroll
        for (int ks = 0; ks < 4; ks++) {
#pragma unroll
            for (int snt = 0; snt < 4; snt++) {
                uint32_t bf[2];
                const int base = (snt * 8 + gid) * 36 + ks * 8 + tig;
                bf[0] = KtU[base];
                bf[1] = KtU[base + 4];
                mma_f16(sc[snt], qa[ks], bf);
            }
        }

        float mt0 = -1e30f, mt1 = -1e30f;
#pragma unroll
        for (int snt = 0; snt < 4; snt++) {
            const int c0 = k0 + snt * 8 + 2 * tig;
            if (c0 > r0)     sc[snt][0] = -1e30f;
            if (c0 + 1 > r0) sc[snt][1] = -1e30f;
            if (c0 > r1)     sc[snt][2] = -1e30f;
            if (c0 + 1 > r1) sc[snt][3] = -1e30f;
            mt0 = fmaxf(mt0, fmaxf(sc[snt][0], sc[snt][1]));
            mt1 = fmaxf(mt1, fmaxf(sc[snt][2], sc[snt][3]));
        }
        mt0 = fmaxf(mt0, __shfl_xor_sync(0xffffffffu, mt0, 1));
        mt0 = fmaxf(mt0, __shfl_xor_sync(0xffffffffu, mt0, 2));
        mt1 = fmaxf(mt1, __shfl_xor_sync(0xffffffffu, mt1, 1));
        mt1 = fmaxf(mt1, __shfl_xor_sync(0xffffffffu, mt1, 2));

        const float nm0 = fmaxf(m0, mt0);
        const float nm1 = fmaxf(m1, mt1);
        const float al0 = __expf(m0 - nm0);
        const float al1 = __expf(m1 - nm1);
        m0 = nm0; m1 = nm1;

        float s0 = 0.f, s1 = 0.f;
#pragma unroll
        for (int snt = 0; snt < 4; snt++) {
            float p0 = __expf(sc[snt][0] - nm0);
            float p1 = __expf(sc[snt][1] - nm0);
            float p2 = __expf(sc[snt][2] - nm1);
            float p3 = __expf(sc[snt][3] - nm1);
            s0 += p0 + p1; s1 += p2 + p3;
            const int col = snt * 8 + 2 * tig;
            *(uint32_t*)&Ps[warp][gid][col]     = h2u(__floats2half2_rn(p0, p1));
            *(uint32_t*)&Ps[warp][gid + 8][col] = h2u(__floats2half2_rn(p2, p3));
        }
        s0 += __shfl_xor_sync(0xffffffffu, s0, 1);
        s0 += __shfl_xor_sync(0xffffffffu, s0, 2);
        s1 += __shfl_xor_sync(0xffffffffu, s1, 1);
        s1 += __shfl_xor_sync(0xffffffffu, s1, 2);
        l0 = l0 * al0 + s0;
        l1 = l1 * al1 + s1;

#pragma unroll
        for (int dnt = 0; dnt < 8; dnt++) {
            oa[dnt][0] *= al0; oa[dnt][1] *= al0;
            oa[dnt][2] *= al1; oa[dnt][3] *= al1;
        }
        __syncwarp();

        // PV: 2 ks x 8 dnt MMAs
        const uint32_t* PsU = (const uint32_t*)&Ps[warp][0][0];
#pragma unroll
        for (int ks = 0; ks < 2; ks++) {
            uint32_t af[4];
            af[0] = PsU[gid * 20 + ks * 8 + tig];
            af[1] = PsU[(gid + 8) * 20 + ks * 8 + tig];
            af[2] = PsU[gid * 20 + ks * 8 + tig + 4];
            af[3] = PsU[(gid + 8) * 20 + ks * 8 + tig + 4];
#pragma unroll
            for (int dnt = 0; dnt < 8; dnt++) {
                uint32_t bf[2];
                bf[0] = VtU[(ks * 8 + tig) * 68 + dnt * 8 + gid];
                bf[1] = VtU[(ks * 8 + tig + 4) * 68 + dnt * 8 + gid];
                mma_f16(oa[dnt], af, bf);
            }
        }
        __syncthreads();
    }

    const float inv0 = 1.f / l0;
    const float inv1 = 1.f / l1;
    __half* Ob = g_O + ((size_t)bh * SS) * DD;
#pragma unroll
    for (int dnt = 0; dnt < 8; dnt++) {
        const int col = dnt * 8 + 2 * tig;
        *(uint32_t*)&Ob[(size_t)r0 * DD + col] =
            h2u(__floats2half2_rn(oa[dnt][0] * inv0, oa[dnt][1] * inv0));
        *(uint32_t*)&Ob[(size_t)r1 * DD + col] =
            h2u(__floats2half2_rn(oa[dnt][2] * inv1, oa[dnt][3] * inv1));
    }
}

// ---------------------------------------------------------------------------
// Output projection fp16 (BK=64, dyn smem). A from g_O half [B,H,S,D]
// (8-half chunks never cross a head boundary), B from g_WoP packed.
// ---------------------------------------------------------------------------
__global__ __launch_bounds__(256, 2) void out_gemm_tc(
    const float* __restrict__ bias, float* __restrict__ out)
{
    extern __shared__ float dyn[];
    const int tid  = threadIdx.x;
    const int lane = tid & 31;
    const int warp = tid >> 5;
    const int wm   = warp >> 1;
    const int wn   = warp & 1;
    const int gid  = lane >> 2;
    const int tig  = lane & 3;
    const int rBase = blockIdx.y * 128;
    const int cBase = blockIdx.x * 128;

    float acc[2][8][4];
#pragma unroll
    for (int i = 0; i < 2; i++)
#pragma unroll
        for (int j = 0; j < 8; j++)
#pragma unroll
            for (int k = 0; k < 4; k++) acc[i][j][k] = 0.f;

    const uint32_t sBase = (uint32_t)__cvta_generic_to_shared(dyn);
    const uint32_t stA = 128 * 36 * 4;
    const uint32_t stB = 32 * 136 * 4;
    const uint32_t bOff = 2 * stA;

    auto loadTile = [&](int buf, int it) {
        const int k0  = it * 64;
        const int k20 = it * 32;
#pragma unroll
        for (int i = 0; i < 4; i++) {
            const int ia  = tid + i * 256;
            const int ar  = ia >> 3;
            const int ac8 = (ia & 7) * 8;
            const int r   = rBase + ar;
            const int b_  = r >> 10, s_ = r & 1023;
            const int k   = k0 + ac8;
            const int h   = k >> 6, d = k & 63;
            cp_async16(sBase + buf * stA + (ar * 36 + (ia & 7) * 4) * 4,
                       g_O + (((size_t)(b_ * HH + h)) * SS + s_) * DD + d);
            const int kr  = ia >> 5;
            const int nc  = (ia & 31) * 4;
            cp_async16(sBase + bOff + buf * stB + (kr * 136 + nc) * 4,
                       g_WoP + (size_t)(k20 + kr) * EE + cBase + nc);
        }
    };

    loadTile(0, 0);
    CP_COMMIT();

    for (int it = 0; it < 16; ++it) {
        if (it + 1 < 16) {
            loadTile((it + 1) & 1, it + 1);
            CP_COMMIT();
            CP_WAIT1();
        } else {
            CP_WAIT0();
        }
        __syncthreads();
        {
            const uint32_t* Ab = (const uint32_t*)dyn + (it & 1) * (128 * 36);
            const uint32_t* Bb = (const uint32_t*)dyn + 2 * (128 * 36) + (it & 1) * (32 * 136);
#pragma unroll
            for (int ks = 0; ks < 4; ks++) {
                uint32_t af[2][4];
#pragma unroll
                for (int mt = 0; mt < 2; mt++) {
                    const int base = (wm * 32 + mt * 16 + gid) * 36 + ks * 8 + tig;
                    af[mt][0] = Ab[base];
                    af[mt][1] = Ab[base + 288];
                    af[mt][2] = Ab[base + 4];
                    af[mt][3] = Ab[base + 292];
                }
                uint32_t bf[8][2];
#pragma unroll
                for (int nt = 0; nt < 8; nt++) {
                    const int col = wn * 64 + nt * 8 + gid;
                    bf[nt][0] = Bb[(ks * 8 + tig) * 136 + col];
                    bf[nt][1] = Bb[(ks * 8 + tig + 4) * 136 + col];
                }
#pragma unroll
                for (int mt = 0; mt < 2; mt++)
#pragma unroll
                    for (int nt = 0; nt < 8; nt++)
                        mma_f16(acc[mt][nt], af[mt], bf[nt]);
            }
        }
        __syncthreads();
    }

#pragma unroll
    for (int mt = 0; mt < 2; mt++)
#pragma unroll
        for (int nt = 0; nt < 8; nt++)
#pragma unroll
            for (int half_ = 0; half_ < 2; half_++) {
                const int r = rBase + wm * 32 + mt * 16 + gid + half_ * 8;
                const int c = cBase + wn * 64 + nt * 8 + 2 * tig;
                float2 v;
                v.x = acc[mt][nt][half_ * 2 + 0] + bias[c];
                v.y = acc[mt][nt][half_ * 2 + 1] + bias[c + 1];
                *(float2*)&out[(size_t)r * EE + c] = v;
            }
}

// ---------------------------------------------------------------------------
extern "C" void kernel_launch(void* const* d_in, const int* in_sizes, int n_in,
                              void* d_out, int out_size)
{
    const float* x = (const float*)d_in[0];
    const float* Wqkv = (const float*)d_in[2];
    const float* bqkv = (const float*)d_in[3];
    const float* Wo = (const float*)d_in[4];
    const float* bo = (const float*)d_in[5];
    float* out = (float*)d_out;

    __half* gX;    cudaGetSymbolAddress((void**)&gX,  g_X);
    uint32_t* gWq; cudaGetSymbolAddress((void**)&gWq, g_WqP);
    uint32_t* gWo; cudaGetSymbolAddress((void**)&gWo, g_WoP);

    cudaFuncSetAttribute(qkv_gemm_tc,
        cudaFuncAttributeMaxDynamicSharedMemorySize, GEMM_SMEM_BYTES);
    cudaFuncSetAttribute(out_gemm_tc,
        cudaFuncAttributeMaxDynamicSharedMemorySize, GEMM_SMEM_BYTES);

    x2h_kernel<<<(BB*SS*EE/4 + 255)/256, 256>>>(x, gX, BB*SS*EE/4);
    packw_kernel<<<((EE/2)*(NE3/4) + 255)/256, 256>>>(Wqkv, gWq, EE, NE3);
    packw_kernel<<<((EE/2)*(EE/4) + 255)/256, 256>>>(Wo, gWo, EE, EE);
    {
        dim3 grid(NE3 / 128, (BB * SS) / 128);   // (24, 32)
        qkv_gemm_tc<<<grid, 256, GEMM_SMEM_BYTES>>>(bqkv);
    }
    {
        dim3 grid(SS / QT, BB * HH);             // (16, 64)
        flash_attn_tc<<<grid, 128>>>();
    }
    {
        dim3 grid(EE / 128, (BB * SS) / 128);    // (8, 32)
        out_gemm_tc<<<grid, 256, GEMM_SMEM_BYTES>>>(bo, out);
    }
}

// round 13
// speedup vs baseline: 2.3089x; 1.0232x over previous
#include <cuda_runtime.h>
#include <cuda_fp16.h>
#include <cstdint>
#include <cstring>

#define BB 4
#define SS 1024
#define EE 1024
#define HH 16
#define DD 64
#define NE3 3072

// GEMM smem: A 2 stages 128x64 half (stride 72 halves), B 2 stages 32x128 half2 (stride 136)
#define GEMM_SMEM_BYTES ((2 * 128 * 36 + 2 * 32 * 136) * 4)   // 71680

// Scratch (no allocations allowed) — fp16 activations, packed fp16 weights
__device__ __half   g_Q[BB*HH*SS*DD];
__device__ __half   g_K[BB*HH*SS*DD];
__device__ uint32_t g_Vp[BB*HH*(SS/2)*DD];   // [bh][key/2][d] = half2(V[2k2][d],V[2k2+1][d])
__device__ __half   g_O[BB*HH*SS*DD];
__device__ __half   g_X[BB*SS*EE];
__device__ uint32_t g_WqP[(EE/2)*NE3];       // [k2][n] = half2(W[2k2][n],W[2k2+1][n])
__device__ uint32_t g_WoP[(EE/2)*EE];

__device__ __forceinline__ uint32_t h2u(__half2 h) {
    uint32_t u; memcpy(&u, &h, 4); return u;
}
__device__ __forceinline__ __half2 u2h(uint32_t u) {
    __half2 h; memcpy(&h, &u, 4); return h;
}

__device__ __forceinline__ void mma_f16(float* c, const uint32_t* a, const uint32_t* b) {
    asm volatile(
        "mma.sync.aligned.m16n8k16.row.col.f32.f16.f16.f32 "
        "{%0,%1,%2,%3},{%4,%5,%6,%7},{%8,%9},{%0,%1,%2,%3};"
        : "+f"(c[0]), "+f"(c[1]), "+f"(c[2]), "+f"(c[3])
        : "r"(a[0]), "r"(a[1]), "r"(a[2]), "r"(a[3]), "r"(b[0]), "r"(b[1]));
}

__device__ __forceinline__ void cp_async16(uint32_t saddr, const void* gaddr) {
    asm volatile("cp.async.cg.shared.global [%0], [%1], 16;"
                 :: "r"(saddr), "l"(gaddr));
}
#define CP_COMMIT() asm volatile("cp.async.commit_group;")
#define CP_WAIT1()  asm volatile("cp.async.wait_group 1;")
#define CP_WAIT0()  asm volatile("cp.async.wait_group 0;")

// ---------------------------------------------------------------------------
// Pre-pass kernels
// ---------------------------------------------------------------------------
__global__ __launch_bounds__(256) void x2h_kernel(
    const float* __restrict__ in, __half* __restrict__ out, int n4)
{
    int i = blockIdx.x * blockDim.x + threadIdx.x;
    if (i < n4) {
        float4 v = ((const float4*)in)[i];
        uint2 r;
        r.x = h2u(__floats2half2_rn(v.x, v.y));
        r.y = h2u(__floats2half2_rn(v.z, v.w));
        ((uint2*)out)[i] = r;
    }
}

// pack W [K][N] f32 -> out [K/2][N] half2 of k-pairs
__global__ __launch_bounds__(256) void packw_kernel(
    const float* __restrict__ in, uint32_t* __restrict__ out, int K, int N)
{
    int i = blockIdx.x * blockDim.x + threadIdx.x;
    int total = (K / 2) * (N / 4);
    if (i < total) {
        int k2 = i / (N / 4);
        int n  = (i % (N / 4)) * 4;
        float4 a = *(const float4*)(in + (size_t)(2 * k2) * N + n);
        float4 b = *(const float4*)(in + (size_t)(2 * k2 + 1) * N + n);
        uint4 r;
        r.x = h2u(__floats2half2_rn(a.x, b.x));
        r.y = h2u(__floats2half2_rn(a.y, b.y));
        r.z = h2u(__floats2half2_rn(a.z, b.z));
        r.w = h2u(__floats2half2_rn(a.w, b.w));
        *(uint4*)(out + (size_t)k2 * N + n) = r;
    }
}

// ---------------------------------------------------------------------------
// GEMM (R12-proven): block 128x128, BK=64 fp16, 8 warps, warp tile 32x64,
// m16n8k16, fp32 accum. Dyn smem, 2 CTAs/SM, proven pipeline.
// ---------------------------------------------------------------------------
__global__ __launch_bounds__(256, 2) void qkv_gemm_tc(
    const float* __restrict__ bias)
{
    extern __shared__ float dyn[];
    const int tid  = threadIdx.x;
    const int lane = tid & 31;
    const int warp = tid >> 5;
    const int wm   = warp >> 1;
    const int wn   = warp & 1;
    const int gid  = lane >> 2;
    const int tig  = lane & 3;
    const int rBase = blockIdx.y * 128;
    const int cBase = blockIdx.x * 128;

    float acc[2][8][4];
#pragma unroll
    for (int i = 0; i < 2; i++)
#pragma unroll
        for (int j = 0; j < 8; j++)
#pragma unroll
            for (int k = 0; k < 4; k++) acc[i][j][k] = 0.f;

    const uint32_t sBase = (uint32_t)__cvta_generic_to_shared(dyn);
    const uint32_t stA = 128 * 36 * 4;
    const uint32_t stB = 32 * 136 * 4;
    const uint32_t bOff = 2 * stA;

    auto loadTile = [&](int buf, int it) {
        const int k0  = it * 64;
        const int k20 = it * 32;
#pragma unroll
        for (int i = 0; i < 4; i++) {
            const int ia  = tid + i * 256;
            const int ar  = ia >> 3;
            const int ac8 = (ia & 7) * 8;
            cp_async16(sBase + buf * stA + (ar * 36 + (ia & 7) * 4) * 4,
                       g_X + (size_t)(rBase + ar) * EE + k0 + ac8);
            const int kr  = ia >> 5;
            const int nc  = (ia & 31) * 4;
            cp_async16(sBase + bOff + buf * stB + (kr * 136 + nc) * 4,
                       g_WqP + (size_t)(k20 + kr) * NE3 + cBase + nc);
        }
    };

    loadTile(0, 0);
    CP_COMMIT();

    for (int it = 0; it < 16; ++it) {
        if (it + 1 < 16) {
            loadTile((it + 1) & 1, it + 1);
            CP_COMMIT();
            CP_WAIT1();
        } else {
            CP_WAIT0();
        }
        __syncthreads();
        {
            const uint32_t* Ab = (const uint32_t*)dyn + (it & 1) * (128 * 36);
            const uint32_t* Bb = (const uint32_t*)dyn + 2 * (128 * 36) + (it & 1) * (32 * 136);
#pragma unroll
            for (int ks = 0; ks < 4; ks++) {
                uint32_t af[2][4];
#pragma unroll
                for (int mt = 0; mt < 2; mt++) {
                    const int base = (wm * 32 + mt * 16 + gid) * 36 + ks * 8 + tig;
                    af[mt][0] = Ab[base];
                    af[mt][1] = Ab[base + 288];
                    af[mt][2] = Ab[base + 4];
                    af[mt][3] = Ab[base + 292];
                }
                uint32_t bf[8][2];
#pragma unroll
                for (int nt = 0; nt < 8; nt++) {
                    const int col = wn * 64 + nt * 8 + gid;
                    bf[nt][0] = Bb[(ks * 8 + tig) * 136 + col];
                    bf[nt][1] = Bb[(ks * 8 + tig + 4) * 136 + col];
                }
#pragma unroll
                for (int mt = 0; mt < 2; mt++)
#pragma unroll
                    for (int nt = 0; nt < 8; nt++)
                        mma_f16(acc[mt][nt], af[mt], bf[nt]);
            }
        }
        __syncthreads();
    }

#pragma unroll
    for (int mt = 0; mt < 2; mt++)
#pragma unroll
        for (int nt = 0; nt < 8; nt++)
#pragma unroll
            for (int half_ = 0; half_ < 2; half_++) {
                const int r = rBase + wm * 32 + mt * 16 + gid + half_ * 8;
                const int c = cBase + wn * 64 + nt * 8 + 2 * tig;
                float vx = acc[mt][nt][half_ * 2 + 0] + bias[c];
                float vy = acc[mt][nt][half_ * 2 + 1] + bias[c + 1];
                const int b_ = r >> 10, s_ = r & 1023;
                const int which = c >> 10;
                const int e = c & 1023;
                const int h = e >> 6, d = e & 63;
                const int bh = b_ * HH + h;
                if (which == 2) {
                    __half* vp = (__half*)g_Vp;
                    size_t base = (((size_t)bh * (SS/2) + (s_ >> 1)) * DD + d) * 2 + (s_ & 1);
                    vp[base]     = __float2half_rn(vx);
                    vp[base + 2] = __float2half_rn(vy);
                } else {
                    __half* dst = (which == 0) ? g_Q : g_K;
                    *(uint32_t*)&dst[((size_t)bh * SS + s_) * DD + d] =
                        h2u(__floats2half2_rn(vx, vy));
                }
            }
}

// ---------------------------------------------------------------------------
// Flash attention fp16: QT=64 (4 warps), KT=64 keys/tile, m16n8k16.
// Per tile: QK 8snt x 4ks MMAs, one softmax rescale, PV 4ks x 8dnt MMAs.
// Smem 45KB static (fits 48KB). Same conflict-free stride algebra as R12.
// ---------------------------------------------------------------------------
#define QT 64
#define KT 64
__global__ __launch_bounds__(128) void flash_attn_tc()
{
    __shared__ __half   Ks[2][KT][72];      // [key][d]
    __shared__ uint32_t Vs[2][KT/2][68];    // [k2][d] half2-packed
    __shared__ __half   Ps[4][16][72];      // per-warp P tile [row][key]

    const int tid  = threadIdx.x;
    const int lane = tid & 31;
    const int warp = tid >> 5;
    const int gid  = lane >> 2;
    const int tig  = lane & 3;
    const int bh   = blockIdx.y;
    const int q0   = blockIdx.x * QT;
    const int r0   = q0 + warp * 16 + gid;
    const int r1   = r0 + 8;

    // Q fragments, scaled by 0.125 (exponent-only, fp16-exact)
    uint32_t qa[4][4];
    {
        const __half* Qb = g_Q + ((size_t)bh * SS) * DD;
        const __half2 sc2 = __floats2half2_rn(0.125f, 0.125f);
#pragma unroll
        for (int ks = 0; ks < 4; ks++) {
            uint32_t u0 = *(const uint32_t*)&Qb[(size_t)r0 * DD + ks * 16 + 2 * tig];
            uint32_t u1 = *(const uint32_t*)&Qb[(size_t)r1 * DD + ks * 16 + 2 * tig];
            uint32_t u2 = *(const uint32_t*)&Qb[(size_t)r0 * DD + ks * 16 + 2 * tig + 8];
            uint32_t u3 = *(const uint32_t*)&Qb[(size_t)r1 * DD + ks * 16 + 2 * tig + 8];
            qa[ks][0] = h2u(__hmul2(u2h(u0), sc2));
            qa[ks][1] = h2u(__hmul2(u2h(u1), sc2));
            qa[ks][2] = h2u(__hmul2(u2h(u2), sc2));
            qa[ks][3] = h2u(__hmul2(u2h(u3), sc2));
        }
    }

    float m0 = -1e30f, m1 = -1e30f, l0 = 0.f, l1 = 0.f;
    float oa[8][4];
#pragma unroll
    for (int i = 0; i < 8; i++)
#pragma unroll
        for (int j = 0; j < 4; j++) oa[i][j] = 0.f;

    const __half* Kb = g_K + ((size_t)bh * SS) * DD;
    const uint32_t* Vb = g_Vp + (size_t)bh * (SS/2) * DD;
    const uint32_t sK = (uint32_t)__cvta_generic_to_shared(&Ks[0][0][0]);
    const uint32_t sV = (uint32_t)__cvta_generic_to_shared(&Vs[0][0][0]);
    const uint32_t stK = KT * 72 * 2;
    const uint32_t stV = (KT/2) * 68 * 4;

    auto loadTile = [&](int buf, int k0) {
#pragma unroll
        for (int i = 0; i < 4; i++) {
            const int idx = tid + i * 128;          // 0..511
            const int key = idx >> 3;               // 0..63
            const int c8  = (idx & 7) * 8;          // halves
            cp_async16(sK + buf * stK + (key * 72 + c8) * 2,
                       Kb + (size_t)(k0 + key) * DD + c8);
            const int k2  = idx >> 4;               // 0..31
            const int c4  = (idx & 15) * 4;         // half2 units
            cp_async16(sV + buf * stV + (k2 * 68 + c4) * 4,
                       Vb + (size_t)(k0 / 2 + k2) * DD + c4);
        }
    };

    const int nkt = blockIdx.x + 1;    // causal, KT == QT
    loadTile(0, 0);
    CP_COMMIT();

    for (int kt = 0; kt < nkt; kt++) {
        if (kt + 1 < nkt) {
            loadTile((kt + 1) & 1, (kt + 1) * KT);
            CP_COMMIT();
            CP_WAIT1();
        } else {
            CP_WAIT0();
        }
        __syncthreads();
        const uint32_t* KtU = (const uint32_t*)&Ks[kt & 1][0][0];
        const uint32_t* VtU = &Vs[kt & 1][0][0];
        const int k0 = kt * KT;

        // S = (Q*scale) @ K^T : 4 ks x 8 snt MMAs
        float sc[8][4];
#pragma unroll
        for (int i = 0; i < 8; i++)
#pragma unroll
            for (int j = 0; j < 4; j++) sc[i][j] = 0.f;
#pragma unroll
        for (int ks = 0; ks < 4; ks++) {
#pragma unroll
            for (int snt = 0; snt < 8; snt++) {
                uint32_t bf[2];
                const int base = (snt * 8 + gid) * 36 + ks * 8 + tig;
                bf[0] = KtU[base];
                bf[1] = KtU[base + 4];
                mma_f16(sc[snt], qa[ks], bf);
            }
        }

        float mt0 = -1e30f, mt1 = -1e30f;
#pragma unroll
        for (int snt = 0; snt < 8; snt++) {
            const int c0 = k0 + snt * 8 + 2 * tig;
            if (c0 > r0)     sc[snt][0] = -1e30f;
            if (c0 + 1 > r0) sc[snt][1] = -1e30f;
            if (c0 > r1)     sc[snt][2] = -1e30f;
            if (c0 + 1 > r1) sc[snt][3] = -1e30f;
            mt0 = fmaxf(mt0, fmaxf(sc[snt][0], sc[snt][1]));
            mt1 = fmaxf(mt1, fmaxf(sc[snt][2], sc[snt][3]));
        }
        mt0 = fmaxf(mt0, __shfl_xor_sync(0xffffffffu, mt0, 1));
        mt0 = fmaxf(mt0, __shfl_xor_sync(0xffffffffu, mt0, 2));
        mt1 = fmaxf(mt1, __shfl_xor_sync(0xffffffffu, mt1, 1));
        mt1 = fmaxf(mt1, __shfl_xor_sync(0xffffffffu, mt1, 2));

        const float nm0 = fmaxf(m0, mt0);
        const float nm1 = fmaxf(m1, mt1);
        const float al0 = __expf(m0 - nm0);
        const float al1 = __expf(m1 - nm1);
        m0 = nm0; m1 = nm1;

        float s0 = 0.f, s1 = 0.f;
#pragma unroll
        for (int snt = 0; snt < 8; snt++) {
            float p0 = __expf(sc[snt][0] - nm0);
            float p1 = __expf(sc[snt][1] - nm0);
            float p2 = __expf(sc[snt][2] - nm1);
            float p3 = __expf(sc[snt][3] - nm1);
            s0 += p0 + p1; s1 += p2 + p3;
            const int col = snt * 8 + 2 * tig;
            *(uint32_t*)&Ps[warp][gid][col]     = h2u(__floats2half2_rn(p0, p1));
            *(uint32_t*)&Ps[warp][gid + 8][col] = h2u(__floats2half2_rn(p2, p3));
        }
        s0 += __shfl_xor_sync(0xffffffffu, s0, 1);
        s0 += __shfl_xor_sync(0xffffffffu, s0, 2);
        s1 += __shfl_xor_sync(0xffffffffu, s1, 1);
        s1 += __shfl_xor_sync(0xffffffffu, s1, 2);
        l0 = l0 * al0 + s0;
        l1 = l1 * al1 + s1;

#pragma unroll
        for (int dnt = 0; dnt < 8; dnt++) {
            oa[dnt][0] *= al0; oa[dnt][1] *= al0;
            oa[dnt][2] *= al1; oa[dnt][3] *= al1;
        }
        __syncwarp();

        // PV: 4 ks x 8 dnt MMAs (P rows stride 36 words)
        const uint32_t* PsU = (const uint32_t*)&Ps[warp][0][0];
#pragma unroll
        for (int ks = 0; ks < 4; ks++) {
            uint32_t af[4];
            af[0] = PsU[gid * 36 + ks * 8 + tig];
            af[1] = PsU[(gid + 8) * 36 + ks * 8 + tig];
            af[2] = PsU[gid * 36 + ks * 8 + tig + 4];
            af[3] = PsU[(gid + 8) * 36 + ks * 8 + tig + 4];
#pragma unroll
            for (int dnt = 0; dnt < 8; dnt++) {
                uint32_t bf[2];
                bf[0] = VtU[(ks * 8 + tig) * 68 + dnt * 8 + gid];
                bf[1] = VtU[(ks * 8 + tig + 4) * 68 + dnt * 8 + gid];
                mma_f16(oa[dnt], af, bf);
            }
        }
        __syncthreads();
    }

    const float inv0 = 1.f / l0;
    const float inv1 = 1.f / l1;
    __half* Ob = g_O + ((size_t)bh * SS) * DD;
#pragma unroll
    for (int dnt = 0; dnt < 8; dnt++) {
        const int col = dnt * 8 + 2 * tig;
        *(uint32_t*)&Ob[(size_t)r0 * DD + col] =
            h2u(__floats2half2_rn(oa[dnt][0] * inv0, oa[dnt][1] * inv0));
        *(uint32_t*)&Ob[(size_t)r1 * DD + col] =
            h2u(__floats2half2_rn(oa[dnt][2] * inv1, oa[dnt][3] * inv1));
    }
}

// ---------------------------------------------------------------------------
// Output projection fp16 (R12-proven, BK=64, dyn smem).
// ---------------------------------------------------------------------------
__global__ __launch_bounds__(256, 2) void out_gemm_tc(
    const float* __restrict__ bias, float* __restrict__ out)
{
    extern __shared__ float dyn[];
    const int tid  = threadIdx.x;
    const int lane = tid & 31;
    const int warp = tid >> 5;
    const int wm   = warp >> 1;
    const int wn   = warp & 1;
    const int gid  = lane >> 2;
    const int tig  = lane & 3;
    const int rBase = blockIdx.y * 128;
    const int cBase = blockIdx.x * 128;

    float acc[2][8][4];
#pragma unroll
    for (int i = 0; i < 2; i++)
#pragma unroll
        for (int j = 0; j < 8; j++)
#pragma unroll
            for (int k = 0; k < 4; k++) acc[i][j][k] = 0.f;

    const uint32_t sBase = (uint32_t)__cvta_generic_to_shared(dyn);
    const uint32_t stA = 128 * 36 * 4;
    const uint32_t stB = 32 * 136 * 4;
    const uint32_t bOff = 2 * stA;

    auto loadTile = [&](int buf, int it) {
        const int k0  = it * 64;
        const int k20 = it * 32;
#pragma unroll
        for (int i = 0; i < 4; i++) {
            const int ia  = tid + i * 256;
            const int ar  = ia >> 3;
            const int ac8 = (ia & 7) * 8;
            const int r   = rBase + ar;
            const int b_  = r >> 10, s_ = r & 1023;
            const int k   = k0 + ac8;
            const int h   = k >> 6, d = k & 63;
            cp_async16(sBase + buf * stA + (ar * 36 + (ia & 7) * 4) * 4,
                       g_O + (((size_t)(b_ * HH + h)) * SS + s_) * DD + d);
            const int kr  = ia >> 5;
            const int nc  = (ia & 31) * 4;
            cp_async16(sBase + bOff + buf * stB + (kr * 136 + nc) * 4,
                       g_WoP + (size_t)(k20 + kr) * EE + cBase + nc);
        }
    };

    loadTile(0, 0);
    CP_COMMIT();

    for (int it = 0; it < 16; ++it) {
        if (it + 1 < 16) {
            loadTile((it + 1) & 1, it + 1);
            CP_COMMIT();
            CP_WAIT1();
        } else {
            CP_WAIT0();
        }
        __syncthreads();
        {
            const uint32_t* Ab = (const uint32_t*)dyn + (it & 1) * (128 * 36);
            const uint32_t* Bb = (const uint32_t*)dyn + 2 * (128 * 36) + (it & 1) * (32 * 136);
#pragma unroll
            for (int ks = 0; ks < 4; ks++) {
                uint32_t af[2][4];
#pragma unroll
                for (int mt = 0; mt < 2; mt++) {
                    const int base = (wm * 32 + mt * 16 + gid) * 36 + ks * 8 + tig;
                    af[mt][0] = Ab[base];
                    af[mt][1] = Ab[base + 288];
                    af[mt][2] = Ab[base + 4];
                    af[mt][3] = Ab[base + 292];
                }
                uint32_t bf[8][2];
#pragma unroll
                for (int nt = 0; nt < 8; nt++) {
                    const int col = wn * 64 + nt * 8 + gid;
                    bf[nt][0] = Bb[(ks * 8 + tig) * 136 + col];
                    bf[nt][1] = Bb[(ks * 8 + tig + 4) * 136 + col];
                }
#pragma unroll
                for (int mt = 0; mt < 2; mt++)
#pragma unroll
                    for (int nt = 0; nt < 8; nt++)
                        mma_f16(acc[mt][nt], af[mt], bf[nt]);
            }
        }
        __syncthreads();
    }

#pragma unroll
    for (int mt = 0; mt < 2; mt++)
#pragma unroll
        for (int nt = 0; nt < 8; nt++)
#pragma unroll
            for (int half_ = 0; half_ < 2; half_++) {
                const int r = rBase + wm * 32 + mt * 16 + gid + half_ * 8;
                const int c = cBase + wn * 64 + nt * 8 + 2 * tig;
                float2 v;
                v.x = acc[mt][nt][half_ * 2 + 0] + bias[c];
                v.y = acc[mt][nt][half_ * 2 + 1] + bias[c + 1];
                *(float2*)&out[(size_t)r * EE + c] = v;
            }
}

// ---------------------------------------------------------------------------
extern "C" void kernel_launch(void* const* d_in, const int* in_sizes, int n_in,
                              void* d_out, int out_size)
{
    const float* x = (const float*)d_in[0];
    const float* Wqkv = (const float*)d_in[2];
    const float* bqkv = (const float*)d_in[3];
    const float* Wo = (const float*)d_in[4];
    const float* bo = (const float*)d_in[5];
    float* out = (float*)d_out;

    __half* gX;    cudaGetSymbolAddress((void**)&gX,  g_X);
    uint32_t* gWq; cudaGetSymbolAddress((void**)&gWq, g_WqP);
    uint32_t* gWo; cudaGetSymbolAddress((void**)&gWo, g_WoP);

    cudaFuncSetAttribute(qkv_gemm_tc,
        cudaFuncAttributeMaxDynamicSharedMemorySize, GEMM_SMEM_BYTES);
    cudaFuncSetAttribute(out_gemm_tc,
        cudaFuncAttributeMaxDynamicSharedMemorySize, GEMM_SMEM_BYTES);

    x2h_kernel<<<(BB*SS*EE/4 + 255)/256, 256>>>(x, gX, BB*SS*EE/4);
    packw_kernel<<<((EE/2)*(NE3/4) + 255)/256, 256>>>(Wqkv, gWq, EE, NE3);
    packw_kernel<<<((EE/2)*(EE/4) + 255)/256, 256>>>(Wo, gWo, EE, EE);
    {
        dim3 grid(NE3 / 128, (BB * SS) / 128);   // (24, 32)
        qkv_gemm_tc<<<grid, 256, GEMM_SMEM_BYTES>>>(bqkv);
    }
    {
        dim3 grid(SS / QT, BB * HH);             // (16, 64)
        flash_attn_tc<<<grid, 128>>>();
    }
    {
        dim3 grid(EE / 128, (BB * SS) / 128);    // (8, 32)
        out_gemm_tc<<<grid, 256, GEMM_SMEM_BYTES>>>(bo, out);
    }
}

// round 14
// speedup vs baseline: 2.3104x; 1.0006x over previous
#include <cuda_runtime.h>
#include <cuda_fp16.h>
#include <cstdint>
#include <cstring>

#define BB 4
#define SS 1024
#define EE 1024
#define HH 16
#define DD 64
#define NE3 3072

// GEMM smem: A 2 stages [128][72] half + B 2 stages [128][72] half
#define GEMM_SMEM_BYTES (4 * 128 * 72 * 2)   // 73728

// Scratch (no allocations allowed)
__device__ __half   g_Q[BB*HH*SS*DD];
__device__ __half   g_K[BB*HH*SS*DD];
__device__ uint32_t g_Vp[BB*HH*(SS/2)*DD];   // [bh][key/2][d] packed half2 k-pairs
__device__ __half   g_O[BB*HH*SS*DD];
__device__ __half   g_X[BB*SS*EE];
__device__ __half   g_WqT[NE3*EE];           // Wqkv transposed [n][k] fp16
__device__ __half   g_WoT[EE*EE];            // Wo transposed [n][k] fp16

__device__ __forceinline__ uint32_t h2u(__half2 h) {
    uint32_t u; memcpy(&u, &h, 4); return u;
}
__device__ __forceinline__ __half2 u2h(uint32_t u) {
    __half2 h; memcpy(&h, &u, 4); return h;
}

__device__ __forceinline__ void mma_f16(float* c, const uint32_t* a, const uint32_t* b) {
    asm volatile(
        "mma.sync.aligned.m16n8k16.row.col.f32.f16.f16.f32 "
        "{%0,%1,%2,%3},{%4,%5,%6,%7},{%8,%9},{%0,%1,%2,%3};"
        : "+f"(c[0]), "+f"(c[1]), "+f"(c[2]), "+f"(c[3])
        : "r"(a[0]), "r"(a[1]), "r"(a[2]), "r"(a[3]), "r"(b[0]), "r"(b[1]));
}

__device__ __forceinline__ void ldsm_x4(uint32_t* r, uint32_t addr) {
    asm volatile("ldmatrix.sync.aligned.m8n8.x4.shared.b16 {%0,%1,%2,%3}, [%4];"
                 : "=r"(r[0]), "=r"(r[1]), "=r"(r[2]), "=r"(r[3]) : "r"(addr));
}

__device__ __forceinline__ void cp_async16(uint32_t saddr, const void* gaddr) {
    asm volatile("cp.async.cg.shared.global [%0], [%1], 16;"
                 :: "r"(saddr), "l"(gaddr));
}
#define CP_COMMIT() asm volatile("cp.async.commit_group;")
#define CP_WAIT1()  asm volatile("cp.async.wait_group 1;")
#define CP_WAIT0()  asm volatile("cp.async.wait_group 0;")

// ---------------------------------------------------------------------------
// Pre-pass kernels
// ---------------------------------------------------------------------------
__global__ __launch_bounds__(256) void x2h_kernel(
    const float* __restrict__ in, __half* __restrict__ out, int n4)
{
    int i = blockIdx.x * blockDim.x + threadIdx.x;
    if (i < n4) {
        float4 v = ((const float4*)in)[i];
        uint2 r;
        r.x = h2u(__floats2half2_rn(v.x, v.y));
        r.y = h2u(__floats2half2_rn(v.z, v.w));
        ((uint2*)out)[i] = r;
    }
}

// tiled transpose: in [K][N] f32 -> out [N][K] fp16 (coalesced both sides)
__global__ __launch_bounds__(256) void transposeh_kernel(
    const float* __restrict__ in, __half* __restrict__ out, int K, int N)
{
    __shared__ float t[32][33];
    const int n0 = blockIdx.x * 32, k0 = blockIdx.y * 32;
    for (int i = threadIdx.y; i < 32; i += 8)
        t[i][threadIdx.x] = in[(size_t)(k0 + i) * N + n0 + threadIdx.x];
    __syncthreads();
    for (int i = threadIdx.y; i < 32; i += 8)
        out[(size_t)(n0 + i) * K + k0 + threadIdx.x] =
            __float2half_rn(t[threadIdx.x][i]);
}

// ---------------------------------------------------------------------------
// GEMM: block 128x128, BK=64 fp16, 8 warps (4m x 2n), warp tile 32x64,
// m16n8k16, fp32 accum. Smem: A [m][72]h, B [n][72]h (both k-contiguous).
// Fragments via ldmatrix.x4 (24 LDSM/warp/iter vs 96 LDS). 2 CTAs/SM.
// Pipeline: issue(it+1) -> commit -> WAIT1 -> sync -> compute(it) -> sync.
// ---------------------------------------------------------------------------
__global__ __launch_bounds__(256, 2) void qkv_gemm_tc(
    const float* __restrict__ bias)
{
    extern __shared__ __half dyn[];
    const int tid  = threadIdx.x;
    const int lane = tid & 31;
    const int warp = tid >> 5;
    const int wm   = warp >> 1;
    const int wn   = warp & 1;
    const int gid  = lane >> 2;
    const int tig  = lane & 3;
    const int rBase = blockIdx.y * 128;
    const int cBase = blockIdx.x * 128;

    float acc[2][8][4];
#pragma unroll
    for (int i = 0; i < 2; i++)
#pragma unroll
        for (int j = 0; j < 8; j++)
#pragma unroll
            for (int k = 0; k < 4; k++) acc[i][j][k] = 0.f;

    const uint32_t sBase = (uint32_t)__cvta_generic_to_shared(dyn);
    const uint32_t stA = 128 * 72 * 2;      // 18432 B per stage
    const uint32_t bOff = 2 * stA;

    auto loadTile = [&](int buf, int it) {
        const int k0 = it * 64;
#pragma unroll
        for (int i = 0; i < 4; i++) {
            const int ia  = tid + i * 256;
            const int row = ia >> 3;            // 0..127
            const int c8  = (ia & 7) * 8;       // halves
            cp_async16(sBase + buf * stA + (row * 72 + c8) * 2,
                       g_X + (size_t)(rBase + row) * EE + k0 + c8);
            cp_async16(sBase + bOff + buf * stA + (row * 72 + c8) * 2,
                       g_WqT + (size_t)(cBase + row) * EE + k0 + c8);
        }
    };

    // ldmatrix per-lane base addresses
    const uint32_t aFragBase = sBase +
        ((wm * 32 + (lane & 15)) * 72 + (lane >> 4) * 8) * 2;
    const uint32_t bFragBase = sBase + bOff +
        ((wn * 64 + (lane & 7) + (lane >> 4) * 8) * 72 + ((lane >> 3) & 1) * 8) * 2;

    loadTile(0, 0);
    CP_COMMIT();

    for (int it = 0; it < 16; ++it) {
        if (it + 1 < 16) {
            loadTile((it + 1) & 1, it + 1);
            CP_COMMIT();
            CP_WAIT1();
        } else {
            CP_WAIT0();
        }
        __syncthreads();
        const uint32_t so = (it & 1) * stA;
#pragma unroll
        for (int ks = 0; ks < 4; ks++) {
            uint32_t af[2][4];
            ldsm_x4(af[0], aFragBase + so + ks * 32);
            ldsm_x4(af[1], aFragBase + so + 16 * 72 * 2 + ks * 32);
            uint32_t bfp[16];    // [ntp]{bf[2ntp][0],bf[2ntp][1],bf[2ntp+1][0],bf[2ntp+1][1]}
#pragma unroll
            for (int ntp = 0; ntp < 4; ntp++)
                ldsm_x4(&bfp[ntp * 4], bFragBase + so + ntp * 16 * 72 * 2 + ks * 32);
#pragma unroll
            for (int mt = 0; mt < 2; mt++)
#pragma unroll
                for (int nt = 0; nt < 8; nt++)
                    mma_f16(acc[mt][nt], af[mt], &bfp[(nt >> 1) * 4 + (nt & 1) * 2]);
        }
        __syncthreads();
    }

    // epilogue: bias + fp16, scatter to Q/K (half2) and Vp (k-pair packed)
#pragma unroll
    for (int mt = 0; mt < 2; mt++)
#pragma unroll
        for (int nt = 0; nt < 8; nt++)
#pragma unroll
            for (int half_ = 0; half_ < 2; half_++) {
                const int r = rBase + wm * 32 + mt * 16 + gid + half_ * 8;
                const int c = cBase + wn * 64 + nt * 8 + 2 * tig;
                float vx = acc[mt][nt][half_ * 2 + 0] + bias[c];
                float vy = acc[mt][nt][half_ * 2 + 1] + bias[c + 1];
                const int b_ = r >> 10, s_ = r & 1023;
                const int which = c >> 10;
                const int e = c & 1023;
                const int h = e >> 6, d = e & 63;
                const int bh = b_ * HH + h;
                if (which == 2) {
                    __half* vp = (__half*)g_Vp;
                    size_t base = (((size_t)bh * (SS/2) + (s_ >> 1)) * DD + d) * 2 + (s_ & 1);
                    vp[base]     = __float2half_rn(vx);
                    vp[base + 2] = __float2half_rn(vy);
                } else {
                    __half* dst = (which == 0) ? g_Q : g_K;
                    *(uint32_t*)&dst[((size_t)bh * SS + s_) * DD + d] =
                        h2u(__floats2half2_rn(vx, vy));
                }
            }
}

// ---------------------------------------------------------------------------
// Flash attention fp16 (unchanged R13): QT=64, KT=64, m16n8k16.
// ---------------------------------------------------------------------------
#define QT 64
#define KT 64
__global__ __launch_bounds__(128) void flash_attn_tc()
{
    __shared__ __half   Ks[2][KT][72];
    __shared__ uint32_t Vs[2][KT/2][68];
    __shared__ __half   Ps[4][16][72];

    const int tid  = threadIdx.x;
    const int lane = tid & 31;
    const int warp = tid >> 5;
    const int gid  = lane >> 2;
    const int tig  = lane & 3;
    const int bh   = blockIdx.y;
    const int q0   = blockIdx.x * QT;
    const int r0   = q0 + warp * 16 + gid;
    const int r1   = r0 + 8;

    uint32_t qa[4][4];
    {
        const __half* Qb = g_Q + ((size_t)bh * SS) * DD;
        const __half2 sc2 = __floats2half2_rn(0.125f, 0.125f);
#pragma unroll
        for (int ks = 0; ks < 4; ks++) {
            uint32_t u0 = *(const uint32_t*)&Qb[(size_t)r0 * DD + ks * 16 + 2 * tig];
            uint32_t u1 = *(const uint32_t*)&Qb[(size_t)r1 * DD + ks * 16 + 2 * tig];
            uint32_t u2 = *(const uint32_t*)&Qb[(size_t)r0 * DD + ks * 16 + 2 * tig + 8];
            uint32_t u3 = *(const uint32_t*)&Qb[(size_t)r1 * DD + ks * 16 + 2 * tig + 8];
            qa[ks][0] = h2u(__hmul2(u2h(u0), sc2));
            qa[ks][1] = h2u(__hmul2(u2h(u1), sc2));
            qa[ks][2] = h2u(__hmul2(u2h(u2), sc2));
            qa[ks][3] = h2u(__hmul2(u2h(u3), sc2));
        }
    }

    float m0 = -1e30f, m1 = -1e30f, l0 = 0.f, l1 = 0.f;
    float oa[8][4];
#pragma unroll
    for (int i = 0; i < 8; i++)
#pragma unroll
        for (int j = 0; j < 4; j++) oa[i][j] = 0.f;

    const __half* Kb = g_K + ((size_t)bh * SS) * DD;
    const uint32_t* Vb = g_Vp + (size_t)bh * (SS/2) * DD;
    const uint32_t sK = (uint32_t)__cvta_generic_to_shared(&Ks[0][0][0]);
    const uint32_t sV = (uint32_t)__cvta_generic_to_shared(&Vs[0][0][0]);
    const uint32_t stK = KT * 72 * 2;
    const uint32_t stV = (KT/2) * 68 * 4;

    auto loadTile = [&](int buf, int k0) {
#pragma unroll
        for (int i = 0; i < 4; i++) {
            const int idx = tid + i * 128;
            const int key = idx >> 3;
            const int c8  = (idx & 7) * 8;
            cp_async16(sK + buf * stK + (key * 72 + c8) * 2,
                       Kb + (size_t)(k0 + key) * DD + c8);
            const int k2  = idx >> 4;
            const int c4  = (idx & 15) * 4;
            cp_async16(sV + buf * stV + (k2 * 68 + c4) * 4,
                       Vb + (size_t)(k0 / 2 + k2) * DD + c4);
        }
    };

    const int nkt = blockIdx.x + 1;
    loadTile(0, 0);
    CP_COMMIT();

    for (int kt = 0; kt < nkt; kt++) {
        if (kt + 1 < nkt) {
            loadTile((kt + 1) & 1, (kt + 1) * KT);
            CP_COMMIT();
            CP_WAIT1();
        } else {
            CP_WAIT0();
        }
        __syncthreads();
        const uint32_t* KtU = (const uint32_t*)&Ks[kt & 1][0][0];
        const uint32_t* VtU = &Vs[kt & 1][0][0];
        const int k0 = kt * KT;

        float sc[8][4];
#pragma unroll
        for (int i = 0; i < 8; i++)
#pragma unroll
            for (int j = 0; j < 4; j++) sc[i][j] = 0.f;
#pragma unroll
        for (int ks = 0; ks < 4; ks++) {
#pragma unroll
            for (int snt = 0; snt < 8; snt++) {
                uint32_t bf[2];
                const int base = (snt * 8 + gid) * 36 + ks * 8 + tig;
                bf[0] = KtU[base];
                bf[1] = KtU[base + 4];
                mma_f16(sc[snt], qa[ks], bf);
            }
        }

        float mt0 = -1e30f, mt1 = -1e30f;
#pragma unroll
        for (int snt = 0; snt < 8; snt++) {
            const int c0 = k0 + snt * 8 + 2 * tig;
            if (c0 > r0)     sc[snt][0] = -1e30f;
            if (c0 + 1 > r0) sc[snt][1] = -1e30f;
            if (c0 > r1)     sc[snt][2] = -1e30f;
            if (c0 + 1 > r1) sc[snt][3] = -1e30f;
            mt0 = fmaxf(mt0, fmaxf(sc[snt][0], sc[snt][1]));
            mt1 = fmaxf(mt1, fmaxf(sc[snt][2], sc[snt][3]));
        }
        mt0 = fmaxf(mt0, __shfl_xor_sync(0xffffffffu, mt0, 1));
        mt0 = fmaxf(mt0, __shfl_xor_sync(0xffffffffu, mt0, 2));
        mt1 = fmaxf(mt1, __shfl_xor_sync(0xffffffffu, mt1, 1));
        mt1 = fmaxf(mt1, __shfl_xor_sync(0xffffffffu, mt1, 2));

        const float nm0 = fmaxf(m0, mt0);
        const float nm1 = fmaxf(m1, mt1);
        const float al0 = __expf(m0 - nm0);
        const float al1 = __expf(m1 - nm1);
        m0 = nm0; m1 = nm1;

        float s0 = 0.f, s1 = 0.f;
#pragma unroll
        for (int snt = 0; snt < 8; snt++) {
            float p0 = __expf(sc[snt][0] - nm0);
            float p1 = __expf(sc[snt][1] - nm0);
            float p2 = __expf(sc[snt][2] - nm1);
            float p3 = __expf(sc[snt][3] - nm1);
            s0 += p0 + p1; s1 += p2 + p3;
            const int col = snt * 8 + 2 * tig;
            *(uint32_t*)&Ps[warp][gid][col]     = h2u(__floats2half2_rn(p0, p1));
            *(uint32_t*)&Ps[warp][gid + 8][col] = h2u(__floats2half2_rn(p2, p3));
        }
        s0 += __shfl_xor_sync(0xffffffffu, s0, 1);
        s0 += __shfl_xor_sync(0xffffffffu, s0, 2);
        s1 += __shfl_xor_sync(0xffffffffu, s1, 1);
        s1 += __shfl_xor_sync(0xffffffffu, s1, 2);
        l0 = l0 * al0 + s0;
        l1 = l1 * al1 + s1;

#pragma unroll
        for (int dnt = 0; dnt < 8; dnt++) {
            oa[dnt][0] *= al0; oa[dnt][1] *= al0;
            oa[dnt][2] *= al1; oa[dnt][3] *= al1;
        }
        __syncwarp();

        const uint32_t* PsU = (const uint32_t*)&Ps[warp][0][0];
#pragma unroll
        for (int ks = 0; ks < 4; ks++) {
            uint32_t af[4];
            af[0] = PsU[gid * 36 + ks * 8 + tig];
            af[1] = PsU[(gid + 8) * 36 + ks * 8 + tig];
            af[2] = PsU[gid * 36 + ks * 8 + tig + 4];
            af[3] = PsU[(gid + 8) * 36 + ks * 8 + tig + 4];
#pragma unroll
            for (int dnt = 0; dnt < 8; dnt++) {
                uint32_t bf[2];
                bf[0] = VtU[(ks * 8 + tig) * 68 + dnt * 8 + gid];
                bf[1] = VtU[(ks * 8 + tig + 4) * 68 + dnt * 8 + gid];
                mma_f16(oa[dnt], af, bf);
            }
        }
        __syncthreads();
    }

    const float inv0 = 1.f / l0;
    const float inv1 = 1.f / l1;
    __half* Ob = g_O + ((size_t)bh * SS) * DD;
#pragma unroll
    for (int dnt = 0; dnt < 8; dnt++) {
        const int col = dnt * 8 + 2 * tig;
        *(uint32_t*)&Ob[(size_t)r0 * DD + col] =
            h2u(__floats2half2_rn(oa[dnt][0] * inv0, oa[dnt][1] * inv0));
        *(uint32_t*)&Ob[(size_t)r1 * DD + col] =
            h2u(__floats2half2_rn(oa[dnt][2] * inv1, oa[dnt][3] * inv1));
    }
}

// ---------------------------------------------------------------------------
// Output projection fp16 (ldmatrix + transposed WoT). A from g_O gather.
// ---------------------------------------------------------------------------
__global__ __launch_bounds__(256, 2) void out_gemm_tc(
    const float* __restrict__ bias, float* __restrict__ out)
{
    extern __shared__ __half dyn[];
    const int tid  = threadIdx.x;
    const int lane = tid & 31;
    const int warp = tid >> 5;
    const int wm   = warp >> 1;
    const int wn   = warp & 1;
    const int gid  = lane >> 2;
    const int tig  = lane & 3;
    const int rBase = blockIdx.y * 128;
    const int cBase = blockIdx.x * 128;

    float acc[2][8][4];
#pragma unroll
    for (int i = 0; i < 2; i++)
#pragma unroll
        for (int j = 0; j < 8; j++)
#pragma unroll
            for (int k = 0; k < 4; k++) acc[i][j][k] = 0.f;

    const uint32_t sBase = (uint32_t)__cvta_generic_to_shared(dyn);
    const uint32_t stA = 128 * 72 * 2;
    const uint32_t bOff = 2 * stA;

    auto loadTile = [&](int buf, int it) {
        const int k0 = it * 64;
#pragma unroll
        for (int i = 0; i < 4; i++) {
            const int ia  = tid + i * 256;
            const int row = ia >> 3;
            const int c8  = (ia & 7) * 8;
            const int r   = rBase + row;
            const int b_  = r >> 10, s_ = r & 1023;
            const int k   = k0 + c8;
            const int h   = k >> 6, d = k & 63;
            cp_async16(sBase + buf * stA + (row * 72 + c8) * 2,
                       g_O + (((size_t)(b_ * HH + h)) * SS + s_) * DD + d);
            cp_async16(sBase + bOff + buf * stA + (row * 72 + c8) * 2,
                       g_WoT + (size_t)(cBase + row) * EE + k0 + c8);
        }
    };

    const uint32_t aFragBase = sBase +
        ((wm * 32 + (lane & 15)) * 72 + (lane >> 4) * 8) * 2;
    const uint32_t bFragBase = sBase + bOff +
        ((wn * 64 + (lane & 7) + (lane >> 4) * 8) * 72 + ((lane >> 3) & 1) * 8) * 2;

    loadTile(0, 0);
    CP_COMMIT();

    for (int it = 0; it < 16; ++it) {
        if (it + 1 < 16) {
            loadTile((it + 1) & 1, it + 1);
            CP_COMMIT();
            CP_WAIT1();
        } else {
            CP_WAIT0();
        }
        __syncthreads();
        const uint32_t so = (it & 1) * stA;
#pragma unroll
        for (int ks = 0; ks < 4; ks++) {
            uint32_t af[2][4];
            ldsm_x4(af[0], aFragBase + so + ks * 32);
            ldsm_x4(af[1], aFragBase + so + 16 * 72 * 2 + ks * 32);
            uint32_t bfp[16];
#pragma unroll
            for (int ntp = 0; ntp < 4; ntp++)
                ldsm_x4(&bfp[ntp * 4], bFragBase + so + ntp * 16 * 72 * 2 + ks * 32);
#pragma unroll
            for (int mt = 0; mt < 2; mt++)
#pragma unroll
                for (int nt = 0; nt < 8; nt++)
                    mma_f16(acc[mt][nt], af[mt], &bfp[(nt >> 1) * 4 + (nt & 1) * 2]);
        }
        __syncthreads();
    }

#pragma unroll
    for (int mt = 0; mt < 2; mt++)
#pragma unroll
        for (int nt = 0; nt < 8; nt++)
#pragma unroll
            for (int half_ = 0; half_ < 2; half_++) {
                const int r = rBase + wm * 32 + mt * 16 + gid + half_ * 8;
                const int c = cBase + wn * 64 + nt * 8 + 2 * tig;
                float2 v;
                v.x = acc[mt][nt][half_ * 2 + 0] + bias[c];
                v.y = acc[mt][nt][half_ * 2 + 1] + bias[c + 1];
                *(float2*)&out[(size_t)r * EE + c] = v;
            }
}

// ---------------------------------------------------------------------------
extern "C" void kernel_launch(void* const* d_in, const int* in_sizes, int n_in,
                              void* d_out, int out_size)
{
    const float* x = (const float*)d_in[0];
    const float* Wqkv = (const float*)d_in[2];
    const float* bqkv = (const float*)d_in[3];
    const float* Wo = (const float*)d_in[4];
    const float* bo = (const float*)d_in[5];
    float* out = (float*)d_out;

    __half* gX;  cudaGetSymbolAddress((void**)&gX,  g_X);
    __half* gWq; cudaGetSymbolAddress((void**)&gWq, g_WqT);
    __half* gWo; cudaGetSymbolAddress((void**)&gWo, g_WoT);

    cudaFuncSetAttribute(qkv_gemm_tc,
        cudaFuncAttributeMaxDynamicSharedMemorySize, GEMM_SMEM_BYTES);
    cudaFuncSetAttribute(out_gemm_tc,
        cudaFuncAttributeMaxDynamicSharedMemorySize, GEMM_SMEM_BYTES);

    x2h_kernel<<<(BB*SS*EE/4 + 255)/256, 256>>>(x, gX, BB*SS*EE/4);
    {
        dim3 grid(NE3/32, EE/32);
        transposeh_kernel<<<grid, dim3(32,8)>>>(Wqkv, gWq, EE, NE3);
    }
    {
        dim3 grid(EE/32, EE/32);
        transposeh_kernel<<<grid, dim3(32,8)>>>(Wo, gWo, EE, EE);
    }
    {
        dim3 grid(NE3 / 128, (BB * SS) / 128);   // (24, 32)
        qkv_gemm_tc<<<grid, 256, GEMM_SMEM_BYTES>>>(bqkv);
    }
    {
        dim3 grid(SS / QT, BB * HH);             // (16, 64)
        flash_attn_tc<<<grid, 128>>>();
    }
    {
        dim3 grid(EE / 128, (BB * SS) / 128);    // (8, 32)
        out_gemm_tc<<<grid, 256, GEMM_SMEM_BYTES>>>(bo, out);
    }
}